// round 3
// baseline (speedup 1.0000x reference)
#include <cuda_runtime.h>
#include <cuda_bf16.h>
#include <cstdint>

#define NPTS 2048
#define DIMS 96
#define NTHREADS 1024

// Device scratch (no runtime allocation allowed)
__device__ double g_d2[(size_t)NPTS * NPTS];      // 32 MB, L2-resident
__device__ double g_sq[NPTS];
__device__ double g_rowmin[NPTS];
__device__ int    g_rowarg[NPTS];
__device__ int    g_parent[NPTS];
__device__ int    g_active[NPTS];
__device__ int    g_labels[NPTS];

__device__ __forceinline__ double dinf() {
    return __longlong_as_double(0x7ff0000000000000LL);
}

// lexicographic (value, index) min via warp shuffle
__device__ __forceinline__ void warp_argmin(double& v, int& c) {
    #pragma unroll
    for (int o = 16; o > 0; o >>= 1) {
        double ov = __shfl_down_sync(0xffffffffu, v, o);
        int    oc = __shfl_down_sync(0xffffffffu, c, o);
        if (ov < v || (ov == v && oc < c)) { v = ov; c = oc; }
    }
}

// ---------------------------------------------------------------------------
// Init: squared norms
// ---------------------------------------------------------------------------
__global__ void k_init_sq(const float* __restrict__ x) {
    int i = blockIdx.x * blockDim.x + threadIdx.x;
    if (i >= NPTS) return;
    const float* xr = x + (size_t)i * DIMS;
    double acc = 0.0;
    #pragma unroll 8
    for (int d = 0; d < DIMS; d++) {
        double v = (double)xr[d];
        acc = fma(v, v, acc);
    }
    g_sq[i] = acc;
}

// ---------------------------------------------------------------------------
// Init: full fp64 squared-distance matrix  d2 = max(sq_i + sq_j - 2*dot, 0)
// ---------------------------------------------------------------------------
__global__ void k_init_d2(const float* __restrict__ x) {
    __shared__ float xi[DIMS];
    int i = blockIdx.y;
    int j = blockIdx.x * blockDim.x + threadIdx.x;
    if (threadIdx.x < DIMS) xi[threadIdx.x] = x[(size_t)i * DIMS + threadIdx.x];
    __syncthreads();
    if (j >= NPTS) return;
    if (i == j) {
        g_d2[(size_t)i * NPTS + j] = dinf();
        return;
    }
    const float* xj = x + (size_t)j * DIMS;
    double dot = 0.0;
    #pragma unroll 8
    for (int d = 0; d < DIMS; d++) {
        dot = fma((double)xi[d], (double)xj[d], dot);
    }
    double v = g_sq[i] + g_sq[j] - 2.0 * dot;
    if (v < 0.0) v = 0.0;
    g_d2[(size_t)i * NPTS + j] = v;
}

// ---------------------------------------------------------------------------
// Init: per-row min + argmin (smallest-col tie-break). One block per row.
// ---------------------------------------------------------------------------
__global__ void k_init_rowmin() {
    __shared__ double sv[256];
    __shared__ int    sc[256];
    int r = blockIdx.x;
    int t = threadIdx.x;
    double bv = dinf();
    int bc = NPTS;
    const double* row = g_d2 + (size_t)r * NPTS;
    for (int c = t; c < NPTS; c += 256) {
        double v = row[c];
        if (v < bv) { bv = v; bc = c; }
    }
    sv[t] = bv; sc[t] = bc;
    __syncthreads();
    for (int s = 128; s > 0; s >>= 1) {
        if (t < s) {
            double v2 = sv[t + s]; int c2 = sc[t + s];
            if (v2 < sv[t] || (v2 == sv[t] && c2 < sc[t])) {
                sv[t] = v2; sc[t] = c2;
            }
        }
        __syncthreads();
    }
    if (t == 0) { g_rowmin[r] = sv[0]; g_rowarg[r] = sc[0]; }
}

// ---------------------------------------------------------------------------
// Persistent Ward merge loop: single block, 1024 threads.
// Per iteration:
//   A: block argmin over rowmin -> (i, j); leader does merge bookkeeping.
//   B: build rescan list (rows whose cached NN was i or j).
//   C: issue row-i/row-j loads, then (overlapped) scan OLD values of flagged
//      rows excluding cols i/j, then fp64 Lance-Williams nd computation.
//      rowmin[i] = block-reduce of nd values (no re-read of row i).
//   Finalize: fold (nd_r, i) into flagged rows' scan results.
// ---------------------------------------------------------------------------
__global__ void __launch_bounds__(NTHREADS, 1)
k_ward(int K) {
    __shared__ double s_rowmin[NPTS];          // 16 KB
    __shared__ short  s_rowarg[NPTS];          // 4 KB
    __shared__ unsigned short s_sizes[NPTS];   // 4 KB
    __shared__ unsigned char  s_active[NPTS];  // 2 KB
    __shared__ short  s_list[NPTS];            // 4 KB
    __shared__ double s_redv[32];
    __shared__ int    s_redr[32];
    __shared__ double s_pv[32];
    __shared__ int    s_pc[32];
    __shared__ double s_ndval[16];
    __shared__ int    s_cnt;
    __shared__ int    s_i, s_j;
    __shared__ double s_dij, s_si, s_sj;

    const int t = threadIdx.x;
    const int w = t >> 5, lane = t & 31;
    const double INF = dinf();
    const int m0 = t, m1 = t + NTHREADS;

    // Load state into shared
    for (int r = t; r < NPTS; r += NTHREADS) {
        s_rowmin[r] = g_rowmin[r];
        s_rowarg[r] = (short)g_rowarg[r];
        s_sizes[r]  = 1;
        s_active[r] = 1;
    }
    __syncthreads();

    const int iters = NPTS - K;
    for (int it = 0; it < iters; ++it) {
        // ---- Phase A: global argmin over rowmin (flat-argmin tie order) ----
        double v0 = s_rowmin[m0];
        double v1 = s_rowmin[m1];
        double bv; int br;
        if (v1 < v0) { bv = v1; br = m1; } else { bv = v0; br = m0; }
        warp_argmin(bv, br);
        if (lane == 0) { s_redv[w] = bv; s_redr[w] = br; }
        __syncthreads();                                   // B1
        if (w == 0) {
            double rv = s_redv[lane];
            int    rr = s_redr[lane];
            warp_argmin(rv, rr);
            if (lane == 0) {
                int i = rr, j = (int)s_rowarg[rr];
                if (i > j) { int tmp = i; i = j; j = tmp; }
                s_i = i; s_j = j;
                s_dij = rv;                      // rowmin value == d2[i][j] bit-exact
                s_si = (double)s_sizes[i];
                s_sj = (double)s_sizes[j];
                s_sizes[i] = (unsigned short)(s_sizes[i] + s_sizes[j]);
                s_active[j] = 0;
                s_rowmin[j] = INF;
                g_parent[j] = i;
                s_cnt = 0;
            }
        }
        __syncthreads();                                   // B2
        const int i = s_i, j = s_j;
        const double dij = s_dij, si = s_si, sj = s_sj;

        // ---- Phase B: flags + rescan list (j already inactive) ----
        const bool act0 = s_active[m0] && m0 != i;
        const bool act1 = s_active[m1] && m1 != i;
        const short ra0 = s_rowarg[m0], ra1 = s_rowarg[m1];
        const bool fl0 = act0 && (ra0 == i || ra0 == j);
        const bool fl1 = act1 && (ra1 == i || ra1 == j);
        int pos0 = -1, pos1 = -1;
        if (fl0) { pos0 = atomicAdd(&s_cnt, 1); s_list[pos0] = (short)m0; }
        if (fl1) { pos1 = atomicAdd(&s_cnt, 1); s_list[pos1] = (short)m1; }
        __syncthreads();                                   // B3
        const int cnt = s_cnt;

        // ---- Phase C (issue): row i / row j loads ----
        const double* rowI = g_d2 + (size_t)i * NPTS;
        const double* rowJ = g_d2 + (size_t)j * NPTS;
        double a0 = 0.0, b0 = 0.0, a1 = 0.0, b1 = 0.0;
        if (act0) { a0 = rowI[m0]; b0 = rowJ[m0]; }
        if (act1) { a1 = rowI[m1]; b1 = rowJ[m1]; }

        // ---- Phase D (overlapped): scan OLD values of flagged rows,
        //      excluding column i (stale) — col j / diag excluded via
        //      active[] / inf. Writes s_pv partials (S>1) or s_rowmin (S==1).
        int S = 1;
        if (cnt > 0) {
            while (cnt * (S << 1) <= 32) S <<= 1;
            const int segLen = NPTS / S;
            for (int task = w; task < cnt * S; task += 32) {
                const int q = task / S, seg = task & (S - 1);
                const int r = (int)s_list[q];
                const double* row = g_d2 + (size_t)r * NPTS;
                double sv = INF; int sc = NPTS;
                const int c0 = seg * segLen;
                for (int c = c0 + lane; c < c0 + segLen; c += 32) {
                    if (s_active[c] && c != i) {
                        double v = row[c];
                        if (v < sv) { sv = v; sc = c; }
                    }
                }
                warp_argmin(sv, sc);
                if (lane == 0) {
                    if (S == 1) { s_rowmin[r] = sv; s_rowarg[r] = (short)sc; }
                    else        { s_pv[task] = sv; s_pc[task] = sc; }
                }
            }
        }

        // ---- Phase C (compute): Lance-Williams nd; row-i min from registers ----
        double lv = INF; int lc = NPTS;
        double nd0 = 0.0, nd1 = 0.0;
        if (act0) {
            double sm = (double)s_sizes[m0];
            nd0 = ((si + sm) * a0 + (sj + sm) * b0 - sm * dij) / (si + sj + sm);
            g_d2[(size_t)i * NPTS + m0] = nd0;
            g_d2[(size_t)m0 * NPTS + i] = nd0;
            lv = nd0; lc = m0;
        }
        if (act1) {
            double sm = (double)s_sizes[m1];
            nd1 = ((si + sm) * a1 + (sj + sm) * b1 - sm * dij) / (si + sj + sm);
            g_d2[(size_t)i * NPTS + m1] = nd1;
            g_d2[(size_t)m1 * NPTS + i] = nd1;
            if (nd1 < lv) { lv = nd1; lc = m1; }
        }
        // incremental rowmin improvement for unflagged rows
        if (act0 && !fl0) {
            if (nd0 < s_rowmin[m0] || (nd0 == s_rowmin[m0] && i < ra0)) {
                s_rowmin[m0] = nd0; s_rowarg[m0] = (short)i;
            }
        }
        if (act1 && !fl1) {
            if (nd1 < s_rowmin[m1] || (nd1 == s_rowmin[m1] && i < ra1)) {
                s_rowmin[m1] = nd1; s_rowarg[m1] = (short)i;
            }
        }
        // stash nd for flagged rows when partial-combine path is used
        if (S > 1) {
            if (fl0) s_ndval[pos0] = nd0;
            if (fl1) s_ndval[pos1] = nd1;
        }
        // block-reduce row-i min
        warp_argmin(lv, lc);
        if (lane == 0) { s_redv[w] = lv; s_redr[w] = lc; }
        __syncthreads();                                   // B4

        // ---- Finalize ----
        if (w == 31) {
            double rv = s_redv[lane];
            int    rc = s_redr[lane];
            warp_argmin(rv, rc);
            if (lane == 0) { s_rowmin[i] = rv; s_rowarg[i] = (short)rc; }
        }
        if (S > 1) {
            if (w < cnt) {
                double rv = (lane < S) ? s_pv[w * S + lane] : INF;
                int    rc = (lane < S) ? s_pc[w * S + lane] : NPTS;
                warp_argmin(rv, rc);
                if (lane == 0) {
                    const int r = (int)s_list[w];
                    const double nd = s_ndval[w];
                    if (nd < rv || (nd == rv && i < rc)) { rv = nd; rc = i; }
                    s_rowmin[r] = rv; s_rowarg[r] = (short)rc;
                }
            }
        } else if (cnt > 0) {
            // S==1: scan wrote s_rowmin[r] directly; fold own nd in
            if (fl0) {
                if (nd0 < s_rowmin[m0] || (nd0 == s_rowmin[m0] && i < s_rowarg[m0])) {
                    s_rowmin[m0] = nd0; s_rowarg[m0] = (short)i;
                }
            }
            if (fl1) {
                if (nd1 < s_rowmin[m1] || (nd1 == s_rowmin[m1] && i < s_rowarg[m1])) {
                    s_rowmin[m1] = nd1; s_rowarg[m1] = (short)i;
                }
            }
        }
        __syncthreads();                                   // B5
    }

    // Write back active flags for finalize
    for (int r = t; r < NPTS; r += NTHREADS) g_active[r] = (int)s_active[r];
}

// ---------------------------------------------------------------------------
// Relabel: follow parent chain to active representative; label = rank among
// sorted surviving cluster ids (== np.unique inverse).
// ---------------------------------------------------------------------------
__global__ void k_finalize() {
    int p = blockIdx.x * blockDim.x + threadIdx.x;
    if (p >= NPTS) return;
    int c = p;
    while (!g_active[c]) c = g_parent[c];
    int rank = 0;
    for (int q = 0; q < c; q++) rank += g_active[q];
    g_labels[p] = rank;
}

__global__ void k_writeout(float* __restrict__ out, int K) {
    int idx = blockIdx.x * blockDim.x + threadIdx.x;
    int total = NPTS * K;
    if (idx >= total) return;
    int p = idx / K;
    int c = idx - p * K;
    out[idx] = (g_labels[p] == c) ? 1.0f : 0.0f;
}

// ---------------------------------------------------------------------------
extern "C" void kernel_launch(void* const* d_in, const int* in_sizes, int n_in,
                              void* d_out, int out_size) {
    const float* x = (const float*)d_in[0];
    int K = out_size / NPTS;   // out = [B*N, K] one-hot => K from out_size

    k_init_sq<<<(NPTS + 255) / 256, 256>>>(x);
    k_init_d2<<<dim3(NPTS / 128, NPTS), 128>>>(x);
    k_init_rowmin<<<NPTS, 256>>>();
    k_ward<<<1, NTHREADS>>>(K);
    k_finalize<<<(NPTS + 255) / 256, 256>>>();
    k_writeout<<<(NPTS * K + 255) / 256, 256>>>((float*)d_out, K);
}

// round 4
// speedup vs baseline: 1.5591x; 1.5591x over previous
#include <cuda_runtime.h>
#include <cuda_bf16.h>
#include <cstdint>

#define NPTS 2048
#define DIMS 96
#define NTHREADS 1024

// Device scratch (no runtime allocation allowed)
__device__ double g_d2[(size_t)NPTS * NPTS];      // 32 MB, L2-resident
__device__ double g_sq[NPTS];
__device__ double g_rowmin[NPTS];
__device__ int    g_rowarg[NPTS];
__device__ int    g_parent[NPTS];
__device__ int    g_active[NPTS];
__device__ int    g_labels[NPTS];

__device__ __forceinline__ double dinf() {
    return __longlong_as_double(0x7ff0000000000000LL);
}

// lexicographic (value, index) min via warp shuffle
__device__ __forceinline__ void warp_argmin(double& v, int& c) {
    #pragma unroll
    for (int o = 16; o > 0; o >>= 1) {
        double ov = __shfl_down_sync(0xffffffffu, v, o);
        int    oc = __shfl_down_sync(0xffffffffu, c, o);
        if (ov < v || (ov == v && oc < c)) { v = ov; c = oc; }
    }
}

// ---------------------------------------------------------------------------
__global__ void k_init_sq(const float* __restrict__ x) {
    int i = blockIdx.x * blockDim.x + threadIdx.x;
    if (i >= NPTS) return;
    const float* xr = x + (size_t)i * DIMS;
    double acc = 0.0;
    #pragma unroll 8
    for (int d = 0; d < DIMS; d++) {
        double v = (double)xr[d];
        acc = fma(v, v, acc);
    }
    g_sq[i] = acc;
}

__global__ void k_init_d2(const float* __restrict__ x) {
    __shared__ float xi[DIMS];
    int i = blockIdx.y;
    int j = blockIdx.x * blockDim.x + threadIdx.x;
    if (threadIdx.x < DIMS) xi[threadIdx.x] = x[(size_t)i * DIMS + threadIdx.x];
    __syncthreads();
    if (j >= NPTS) return;
    if (i == j) {
        g_d2[(size_t)i * NPTS + j] = dinf();
        return;
    }
    const float* xj = x + (size_t)j * DIMS;
    double dot = 0.0;
    #pragma unroll 8
    for (int d = 0; d < DIMS; d++) {
        dot = fma((double)xi[d], (double)xj[d], dot);
    }
    double v = g_sq[i] + g_sq[j] - 2.0 * dot;
    if (v < 0.0) v = 0.0;
    g_d2[(size_t)i * NPTS + j] = v;
}

__global__ void k_init_rowmin() {
    __shared__ double sv[256];
    __shared__ int    sc[256];
    int r = blockIdx.x;
    int t = threadIdx.x;
    double bv = dinf();
    int bc = NPTS;
    const double* row = g_d2 + (size_t)r * NPTS;
    for (int c = t; c < NPTS; c += 256) {
        double v = row[c];
        if (v < bv) { bv = v; bc = c; }
    }
    sv[t] = bv; sc[t] = bc;
    __syncthreads();
    for (int s = 128; s > 0; s >>= 1) {
        if (t < s) {
            double v2 = sv[t + s]; int c2 = sc[t + s];
            if (v2 < sv[t] || (v2 == sv[t] && c2 < sc[t])) {
                sv[t] = v2; sc[t] = c2;
            }
        }
        __syncthreads();
    }
    if (t == 0) { g_rowmin[r] = sv[0]; g_rowarg[r] = sc[0]; }
}

// ---------------------------------------------------------------------------
// Persistent Ward merge loop: single block, 1024 threads, compacted
// active-cluster list so fp64 work scales with live cluster count.
// ---------------------------------------------------------------------------
__global__ void __launch_bounds__(NTHREADS, 1)
k_ward(int K) {
    __shared__ double s_rowmin[NPTS];          // 16 KB
    __shared__ short  s_rowarg[NPTS];          // 4 KB
    __shared__ unsigned short s_sizes[NPTS];   // 4 KB
    __shared__ short  s_alist[NPTS];           // 4 KB  active ids (first s_na)
    __shared__ short  s_pos[NPTS];             // 4 KB  id -> list position
    __shared__ short  s_list[NPTS];            // 4 KB  rescan list
    __shared__ double s_redv[32];
    __shared__ int    s_redr[32];
    __shared__ double s_pv[32];
    __shared__ int    s_pc[32];
    __shared__ int    s_cnt, s_na;
    __shared__ int    s_i, s_j;
    __shared__ double s_dij, s_si, s_sj;

    const int t = threadIdx.x;
    const int w = t >> 5, lane = t & 31;
    const double INF = dinf();
    const int m0 = t, m1 = t + NTHREADS;

    for (int r = t; r < NPTS; r += NTHREADS) {
        s_rowmin[r] = g_rowmin[r];
        s_rowarg[r] = (short)g_rowarg[r];
        s_sizes[r]  = 1;
        s_alist[r]  = (short)r;
        s_pos[r]    = (short)r;
    }
    if (t == 0) s_na = NPTS;
    __syncthreads();

    const int iters = NPTS - K;
    for (int it = 0; it < iters; ++it) {
        // ---- Phase A: global argmin over rowmin (flat-argmin tie order) ----
        double v0 = s_rowmin[m0];
        double v1 = s_rowmin[m1];
        double bv; int br;
        if (v1 < v0) { bv = v1; br = m1; } else { bv = v0; br = m0; }
        warp_argmin(bv, br);
        if (lane == 0) { s_redv[w] = bv; s_redr[w] = br; }
        __syncthreads();                                   // B1
        if (w == 0) {
            double rv = s_redv[lane];
            int    rr = s_redr[lane];
            warp_argmin(rv, rr);
            if (lane == 0) {
                int i = rr, j = (int)s_rowarg[rr];
                if (i > j) { int tmp = i; i = j; j = tmp; }
                s_i = i; s_j = j;
                s_dij = rv;
                s_si = (double)s_sizes[i];
                s_sj = (double)s_sizes[j];
                s_sizes[i] = (unsigned short)(s_sizes[i] + s_sizes[j]);
                s_rowmin[j] = INF;
                g_parent[j] = i;
                // remove j from active list (swap with last)
                int pj = (int)s_pos[j];
                int na = s_na - 1;
                short last = s_alist[na];
                s_alist[pj] = last;
                s_pos[last] = (short)pj;
                s_na = na;
                s_cnt = 0;
            }
        }
        __syncthreads();                                   // B2
        const int i = s_i, j = s_j;
        const double dij = s_dij, si = s_si, sj = s_sj;
        const int na = s_na;     // list now holds active ids incl. i

        // ---- Phase C: Lance-Williams over active list (<=2 ids/thread) ----
        int id0 = (m0 < na) ? (int)s_alist[m0] : -1;
        int id1 = (m1 < na) ? (int)s_alist[m1] : -1;
        const bool c0 = (id0 >= 0) && (id0 != i);
        const bool c1 = (id1 >= 0) && (id1 != i);
        const double* rowI = g_d2 + (size_t)i * NPTS;
        const double* rowJ = g_d2 + (size_t)j * NPTS;
        double a0 = 0.0, b0 = 0.0, a1 = 0.0, b1 = 0.0;
        if (c0) { a0 = rowI[id0]; b0 = rowJ[id0]; }
        if (c1) { a1 = rowI[id1]; b1 = rowJ[id1]; }

        double lv = INF; int lc = NPTS;   // row-i min from registers
        if (c0) {
            double sm = (double)s_sizes[id0];
            double nd = ((si + sm) * a0 + (sj + sm) * b0 - sm * dij) / (si + sj + sm);
            g_d2[(size_t)i * NPTS + id0] = nd;
            g_d2[(size_t)id0 * NPTS + i] = nd;
            lv = nd; lc = id0;
            short ra = s_rowarg[id0];
            if (ra == i || ra == j) {
                int p = atomicAdd(&s_cnt, 1); s_list[p] = (short)id0;
            } else if (nd < s_rowmin[id0] || (nd == s_rowmin[id0] && i < ra)) {
                s_rowmin[id0] = nd; s_rowarg[id0] = (short)i;
            }
        }
        if (c1) {
            double sm = (double)s_sizes[id1];
            double nd = ((si + sm) * a1 + (sj + sm) * b1 - sm * dij) / (si + sj + sm);
            g_d2[(size_t)i * NPTS + id1] = nd;
            g_d2[(size_t)id1 * NPTS + i] = nd;
            if (nd < lv || (nd == lv && id1 < lc)) { lv = nd; lc = id1; }
            short ra = s_rowarg[id1];
            if (ra == i || ra == j) {
                int p = atomicAdd(&s_cnt, 1); s_list[p] = (short)id1;
            } else if (nd < s_rowmin[id1] || (nd == s_rowmin[id1] && i < ra)) {
                s_rowmin[id1] = nd; s_rowarg[id1] = (short)i;
            }
        }
        warp_argmin(lv, lc);
        if (lane == 0) { s_redv[w] = lv; s_redr[w] = lc; }
        __syncthreads();                                   // B3
        const int cnt = s_cnt;

        // ---- Phase D: rescan flagged rows over active list (fresh values,
        //      col i already updated, col j not in list). Split rows across
        //      S warps when cnt is small; warp 31 finalizes row i.
        int S = 1;
        if (cnt > 0 && cnt < 16) S = 31 / cnt;             // cnt*S <= 31 (warp 31 free)
        const int segLen = (na + S - 1) / S;

        for (int task = w; task < cnt * S; task += 32) {
            const int q = task / S, seg = task - q * S;
            const int r = (int)s_list[q];
            const double* row = g_d2 + (size_t)r * NPTS;
            double sv = INF; int sc = NPTS;
            const int cEnd = min(na, (seg + 1) * segLen);
            for (int c = seg * segLen + lane; c < cEnd; c += 32) {
                const int id = (int)s_alist[c];
                const double v = row[id];
                if (v < sv || (v == sv && id < sc)) { sv = v; sc = id; }
            }
            warp_argmin(sv, sc);
            if (lane == 0) {
                if (S == 1) { s_rowmin[r] = sv; s_rowarg[r] = (short)sc; }
                else        { s_pv[task] = sv; s_pc[task] = sc; }
            }
        }
        if (w == 31) {  // row-i final reduce
            double rv = s_redv[lane];
            int    rc = s_redr[lane];
            warp_argmin(rv, rc);
            if (lane == 0) { s_rowmin[i] = rv; s_rowarg[i] = (short)rc; }
        }
        __syncthreads();                                   // B4
        if (S > 1) {
            if (w < cnt) {
                double rv = (lane < S) ? s_pv[w * S + lane] : INF;
                int    rc = (lane < S) ? s_pc[w * S + lane] : NPTS;
                warp_argmin(rv, rc);
                if (lane == 0) {
                    const int r = (int)s_list[w];
                    s_rowmin[r] = rv; s_rowarg[r] = (short)rc;
                }
            }
        }
        __syncthreads();                                   // B5
    }

    // Write back active flags for finalize
    for (int r = t; r < NPTS; r += NTHREADS) g_active[r] = 0;
    __syncthreads();
    for (int p = t; p < s_na; p += NTHREADS) g_active[(int)s_alist[p]] = 1;
}

// ---------------------------------------------------------------------------
__global__ void k_finalize() {
    int p = blockIdx.x * blockDim.x + threadIdx.x;
    if (p >= NPTS) return;
    int c = p;
    while (!g_active[c]) c = g_parent[c];
    int rank = 0;
    for (int q = 0; q < c; q++) rank += g_active[q];
    g_labels[p] = rank;
}

__global__ void k_writeout(float* __restrict__ out, int K) {
    int idx = blockIdx.x * blockDim.x + threadIdx.x;
    int total = NPTS * K;
    if (idx >= total) return;
    int p = idx / K;
    int c = idx - p * K;
    out[idx] = (g_labels[p] == c) ? 1.0f : 0.0f;
}

// ---------------------------------------------------------------------------
extern "C" void kernel_launch(void* const* d_in, const int* in_sizes, int n_in,
                              void* d_out, int out_size) {
    const float* x = (const float*)d_in[0];
    int K = out_size / NPTS;   // out = [B*N, K] one-hot => K from out_size

    k_init_sq<<<(NPTS + 255) / 256, 256>>>(x);
    k_init_d2<<<dim3(NPTS / 128, NPTS), 128>>>(x);
    k_init_rowmin<<<NPTS, 256>>>();
    k_ward<<<1, NTHREADS>>>(K);
    k_finalize<<<(NPTS + 255) / 256, 256>>>();
    k_writeout<<<(NPTS * K + 255) / 256, 256>>>((float*)d_out, K);
}

// round 5
// speedup vs baseline: 1.5717x; 1.0080x over previous
#include <cuda_runtime.h>
#include <cuda_bf16.h>
#include <cstdint>

#define NPTS 2048
#define DIMS 96
#define NTHREADS 1024
#define RECIPN (NPTS + 1)

// Device scratch (no runtime allocation allowed)
__device__ double g_d2[(size_t)NPTS * NPTS];      // 32 MB, L2-resident
__device__ double g_sq[NPTS];
__device__ double g_rowmin[NPTS];
__device__ int    g_rowarg[NPTS];
__device__ int    g_parent[NPTS];
__device__ int    g_active[NPTS];
__device__ int    g_labels[NPTS];
__device__ double g_recip[RECIPN];

__device__ __forceinline__ double dinf() {
    return __longlong_as_double(0x7ff0000000000000LL);
}

// lexicographic (value, index) min via warp shuffle
__device__ __forceinline__ void warp_argmin(double& v, int& c) {
    #pragma unroll
    for (int o = 16; o > 0; o >>= 1) {
        double ov = __shfl_down_sync(0xffffffffu, v, o);
        int    oc = __shfl_down_sync(0xffffffffu, c, o);
        if (ov < v || (ov == v && oc < c)) { v = ov; c = oc; }
    }
}

// Markstein correctly-rounded division num/T given r = RN(1/T).
// Returns RN(num/T) exactly (IEEE double, round-to-nearest).
__device__ __forceinline__ double div_exact(double num, double T, double r) {
    double q0 = __dmul_rn(num, r);
    double e  = __fma_rn(-T, q0, num);
    return __fma_rn(e, r, q0);
}

// ---------------------------------------------------------------------------
__global__ void k_init_sq(const float* __restrict__ x) {
    int i = blockIdx.x * blockDim.x + threadIdx.x;
    if (i < RECIPN) g_recip[i] = 1.0 / (double)(i == 0 ? 1 : i);
    if (i >= NPTS) return;
    const float* xr = x + (size_t)i * DIMS;
    double acc = 0.0;
    #pragma unroll 8
    for (int d = 0; d < DIMS; d++) {
        double v = (double)xr[d];
        acc = fma(v, v, acc);
    }
    g_sq[i] = acc;
}

__global__ void k_init_d2(const float* __restrict__ x) {
    __shared__ float xi[DIMS];
    int i = blockIdx.y;
    int j = blockIdx.x * blockDim.x + threadIdx.x;
    if (threadIdx.x < DIMS) xi[threadIdx.x] = x[(size_t)i * DIMS + threadIdx.x];
    __syncthreads();
    if (j >= NPTS) return;
    if (i == j) {
        g_d2[(size_t)i * NPTS + j] = dinf();
        return;
    }
    const float* xj = x + (size_t)j * DIMS;
    double dot = 0.0;
    #pragma unroll 8
    for (int d = 0; d < DIMS; d++) {
        dot = fma((double)xi[d], (double)xj[d], dot);
    }
    double v = g_sq[i] + g_sq[j] - 2.0 * dot;
    if (v < 0.0) v = 0.0;
    g_d2[(size_t)i * NPTS + j] = v;
}

__global__ void k_init_rowmin() {
    __shared__ double sv[256];
    __shared__ int    sc[256];
    int r = blockIdx.x;
    int t = threadIdx.x;
    double bv = dinf();
    int bc = NPTS;
    const double* row = g_d2 + (size_t)r * NPTS;
    for (int c = t; c < NPTS; c += 256) {
        double v = row[c];
        if (v < bv) { bv = v; bc = c; }
    }
    sv[t] = bv; sc[t] = bc;
    __syncthreads();
    for (int s = 128; s > 0; s >>= 1) {
        if (t < s) {
            double v2 = sv[t + s]; int c2 = sc[t + s];
            if (v2 < sv[t] || (v2 == sv[t] && c2 < sc[t])) {
                sv[t] = v2; sc[t] = c2;
            }
        }
        __syncthreads();
    }
    if (t == 0) { g_rowmin[r] = sv[0]; g_rowarg[r] = sc[0]; }
}

// ---------------------------------------------------------------------------
// Persistent Ward merge loop: single block, 1024 threads, compacted
// active-cluster list; division replaced by Markstein exact-div with a
// shared-memory reciprocal table (divisor is always an integer <= NPTS).
// ---------------------------------------------------------------------------
__global__ void __launch_bounds__(NTHREADS, 1)
k_ward(int K) {
    __shared__ double s_rowmin[NPTS];          // 16 KB
    __shared__ short  s_rowarg[NPTS];          // 4 KB
    __shared__ unsigned short s_sizes[NPTS];   // 4 KB
    __shared__ short  s_alist[NPTS];           // 4 KB  active ids (first s_na)
    __shared__ short  s_pos[NPTS];             // 4 KB  id -> list position
    __shared__ short  s_list[NPTS];            // 4 KB  rescan list
    __shared__ double s_redv[32];
    __shared__ int    s_redr[32];
    __shared__ double s_pv[32];
    __shared__ int    s_pc[32];
    __shared__ int    s_cnt, s_na, s_ssi;
    __shared__ int    s_i, s_j;
    __shared__ double s_dij, s_si, s_sj;
    extern __shared__ double s_recip[];        // RECIPN doubles (dynamic)

    const int t = threadIdx.x;
    const int w = t >> 5, lane = t & 31;
    const double INF = dinf();
    const int m0 = t, m1 = t + NTHREADS;

    for (int r = t; r < NPTS; r += NTHREADS) {
        s_rowmin[r] = g_rowmin[r];
        s_rowarg[r] = (short)g_rowarg[r];
        s_sizes[r]  = 1;
        s_alist[r]  = (short)r;
        s_pos[r]    = (short)r;
    }
    for (int r = t; r < RECIPN; r += NTHREADS) s_recip[r] = g_recip[r];
    if (t == 0) s_na = NPTS;
    __syncthreads();

    const int iters = NPTS - K;
    for (int it = 0; it < iters; ++it) {
        // ---- Phase A: global argmin over rowmin (flat-argmin tie order) ----
        double v0 = s_rowmin[m0];
        double v1 = s_rowmin[m1];
        double bv; int br;
        if (v1 < v0) { bv = v1; br = m1; } else { bv = v0; br = m0; }
        warp_argmin(bv, br);
        if (lane == 0) { s_redv[w] = bv; s_redr[w] = br; }
        __syncthreads();                                   // B1
        if (w == 0) {
            double rv = s_redv[lane];
            int    rr = s_redr[lane];
            warp_argmin(rv, rr);
            if (lane == 0) {
                int i = rr, j = (int)s_rowarg[rr];
                if (i > j) { int tmp = i; i = j; j = tmp; }
                s_i = i; s_j = j;
                s_dij = rv;
                int sii = (int)s_sizes[i], sjj = (int)s_sizes[j];
                s_si = (double)sii;
                s_sj = (double)sjj;
                s_ssi = sii + sjj;
                s_sizes[i] = (unsigned short)(sii + sjj);
                s_rowmin[j] = INF;
                g_parent[j] = i;
                // remove j from active list (swap with last)
                int pj = (int)s_pos[j];
                int na = s_na - 1;
                short last = s_alist[na];
                s_alist[pj] = last;
                s_pos[last] = (short)pj;
                s_na = na;
                s_cnt = 0;
            }
        }
        __syncthreads();                                   // B2
        const int i = s_i, j = s_j;
        const double dij = s_dij, si = s_si, sj = s_sj;
        const int ssi = s_ssi;
        const int na = s_na;     // list now holds active ids incl. i

        // ---- Phase C: Lance-Williams over active list (<=2 ids/thread) ----
        int id0 = (m0 < na) ? (int)s_alist[m0] : -1;
        int id1 = (m1 < na) ? (int)s_alist[m1] : -1;
        const bool c0 = (id0 >= 0) && (id0 != i);
        const bool c1 = (id1 >= 0) && (id1 != i);
        const double* rowI = g_d2 + (size_t)i * NPTS;
        const double* rowJ = g_d2 + (size_t)j * NPTS;
        double a0 = 0.0, b0 = 0.0, a1 = 0.0, b1 = 0.0;
        int smi0 = 1, smi1 = 1;
        if (c0) { a0 = rowI[id0]; b0 = rowJ[id0]; smi0 = (int)s_sizes[id0]; }
        if (c1) { a1 = rowI[id1]; b1 = rowJ[id1]; smi1 = (int)s_sizes[id1]; }

        double lv = INF; int lc = NPTS;   // row-i min from registers
        if (c0) {
            double sm = (double)smi0;
            double num = ((si + sm) * a0 + (sj + sm) * b0 - sm * dij);
            double T = (double)(ssi + smi0);
            double nd = div_exact(num, T, s_recip[ssi + smi0]);
            g_d2[(size_t)i * NPTS + id0] = nd;
            g_d2[(size_t)id0 * NPTS + i] = nd;
            lv = nd; lc = id0;
            short ra = s_rowarg[id0];
            if (ra == i || ra == j) {
                int p = atomicAdd(&s_cnt, 1); s_list[p] = (short)id0;
            } else if (nd < s_rowmin[id0] || (nd == s_rowmin[id0] && i < ra)) {
                s_rowmin[id0] = nd; s_rowarg[id0] = (short)i;
            }
        }
        if (c1) {
            double sm = (double)smi1;
            double num = ((si + sm) * a1 + (sj + sm) * b1 - sm * dij);
            double T = (double)(ssi + smi1);
            double nd = div_exact(num, T, s_recip[ssi + smi1]);
            g_d2[(size_t)i * NPTS + id1] = nd;
            g_d2[(size_t)id1 * NPTS + i] = nd;
            if (nd < lv || (nd == lv && id1 < lc)) { lv = nd; lc = id1; }
            short ra = s_rowarg[id1];
            if (ra == i || ra == j) {
                int p = atomicAdd(&s_cnt, 1); s_list[p] = (short)id1;
            } else if (nd < s_rowmin[id1] || (nd == s_rowmin[id1] && i < ra)) {
                s_rowmin[id1] = nd; s_rowarg[id1] = (short)i;
            }
        }
        warp_argmin(lv, lc);
        if (lane == 0) { s_redv[w] = lv; s_redr[w] = lc; }
        __syncthreads();                                   // B3
        const int cnt = s_cnt;

        // ---- Phase D: rescan flagged rows over active list; split rows
        //      across S warps when cnt is small; warp 31 finalizes row i.
        int S = 1;
        if (cnt > 0 && cnt < 16) S = 31 / cnt;             // cnt*S <= 31 (warp 31 free)
        const int segLen = (na + S - 1) / S;

        for (int task = w; task < cnt * S; task += 32) {
            const int q = task / S, seg = task - q * S;
            const int r = (int)s_list[q];
            const double* row = g_d2 + (size_t)r * NPTS;
            double sv = INF; int sc = NPTS;
            const int cEnd = min(na, (seg + 1) * segLen);
            for (int c = seg * segLen + lane; c < cEnd; c += 32) {
                const int id = (int)s_alist[c];
                const double v = row[id];
                if (v < sv || (v == sv && id < sc)) { sv = v; sc = id; }
            }
            warp_argmin(sv, sc);
            if (lane == 0) {
                if (S == 1) { s_rowmin[r] = sv; s_rowarg[r] = (short)sc; }
                else        { s_pv[task] = sv; s_pc[task] = sc; }
            }
        }
        if (w == 31) {  // row-i final reduce
            double rv = s_redv[lane];
            int    rc = s_redr[lane];
            warp_argmin(rv, rc);
            if (lane == 0) { s_rowmin[i] = rv; s_rowarg[i] = (short)rc; }
        }
        __syncthreads();                                   // B4
        if (S > 1) {
            if (w < cnt) {
                double rv = (lane < S) ? s_pv[w * S + lane] : INF;
                int    rc = (lane < S) ? s_pc[w * S + lane] : NPTS;
                warp_argmin(rv, rc);
                if (lane == 0) {
                    const int r = (int)s_list[w];
                    s_rowmin[r] = rv; s_rowarg[r] = (short)rc;
                }
            }
        }
        __syncthreads();                                   // B5
    }

    // Write back active flags for finalize
    for (int r = t; r < NPTS; r += NTHREADS) g_active[r] = 0;
    __syncthreads();
    for (int p = t; p < s_na; p += NTHREADS) g_active[(int)s_alist[p]] = 1;
}

// ---------------------------------------------------------------------------
__global__ void k_finalize() {
    int p = blockIdx.x * blockDim.x + threadIdx.x;
    if (p >= NPTS) return;
    int c = p;
    while (!g_active[c]) c = g_parent[c];
    int rank = 0;
    for (int q = 0; q < c; q++) rank += g_active[q];
    g_labels[p] = rank;
}

__global__ void k_writeout(float* __restrict__ out, int K) {
    int idx = blockIdx.x * blockDim.x + threadIdx.x;
    int total = NPTS * K;
    if (idx >= total) return;
    int p = idx / K;
    int c = idx - p * K;
    out[idx] = (g_labels[p] == c) ? 1.0f : 0.0f;
}

// ---------------------------------------------------------------------------
extern "C" void kernel_launch(void* const* d_in, const int* in_sizes, int n_in,
                              void* d_out, int out_size) {
    const float* x = (const float*)d_in[0];
    int K = out_size / NPTS;   // out = [B*N, K] one-hot => K from out_size

    static int s_attr_done = 0;
    if (!s_attr_done) {
        cudaFuncSetAttribute(k_ward, cudaFuncAttributeMaxDynamicSharedMemorySize,
                             RECIPN * (int)sizeof(double));
        s_attr_done = 1;
    }

    k_init_sq<<<(NPTS + 255) / 256, 256>>>(x);
    k_init_d2<<<dim3(NPTS / 128, NPTS), 128>>>(x);
    k_init_rowmin<<<NPTS, 256>>>();
    k_ward<<<1, NTHREADS, RECIPN * sizeof(double)>>>(K);
    k_finalize<<<(NPTS + 255) / 256, 256>>>();
    k_writeout<<<(NPTS * K + 255) / 256, 256>>>((float*)d_out, K);
}

// round 6
// speedup vs baseline: 9.5931x; 6.1038x over previous
#include <cuda_runtime.h>
#include <cuda_bf16.h>
#include <cstdint>

#define NPTS 2048
#define DIMS 96
#define ROUNDS 80
#define MAXP 1024

// Device scratch (no runtime allocation allowed)
__device__ double g_d2[(size_t)NPTS * NPTS];      // 32 MB
__device__ double g_sq[NPTS];
__device__ int    g_alist[NPTS];
__device__ int    g_na;
__device__ int    g_sizes_i[NPTS];
__device__ int    g_nn[NPTS];
__device__ double g_nnd[NPTS];
__device__ unsigned char g_flag[NPTS];   // merged this round (iA or jA)
__device__ unsigned char g_dead[NPTS];   // permanently dead (was jA)
__device__ int    g_parent[NPTS];
__device__ int    g_active[NPTS];        // survivor after threshold cut
__device__ int    g_labels[NPTS];
// pair arrays (per round)
__device__ int    g_pia[MAXP], g_pja[MAXP], g_psi[MAXP], g_psj[MAXP];
__device__ double g_pdij[MAXP];
__device__ int    g_npairs;
// merge log (all rounds)
__device__ double g_md[NPTS];
__device__ int    g_mj[NPTS];
__device__ int    g_mcnt;
__device__ double g_theta;

__device__ __forceinline__ double dinf() {
    return __longlong_as_double(0x7ff0000000000000LL);
}

// ---------------------------------------------------------------------------
// Init: squared norms + all bookkeeping state
// ---------------------------------------------------------------------------
__global__ void k_init_sq(const float* __restrict__ x) {
    int i = blockIdx.x * blockDim.x + threadIdx.x;
    if (i >= NPTS) return;
    const float* xr = x + (size_t)i * DIMS;
    double acc = 0.0;
    #pragma unroll 8
    for (int d = 0; d < DIMS; d++) {
        double v = (double)xr[d];
        acc = fma(v, v, acc);
    }
    g_sq[i] = acc;
    g_alist[i] = i;
    g_sizes_i[i] = 1;
    g_parent[i] = i;
    g_active[i] = 1;
    g_flag[i] = 0;
    g_dead[i] = 0;
    if (i == 0) { g_na = NPTS; g_npairs = 0; g_mcnt = 0; }
}

// ---------------------------------------------------------------------------
// Init: fp64 squared-distance matrix, symmetric halved (j >= i), identical
// serial-fma arithmetic to the proven-exact kernel.
// ---------------------------------------------------------------------------
__global__ void k_init_d2(const float* __restrict__ x) {
    __shared__ float xi[DIMS];
    int i = blockIdx.y;
    int j = blockIdx.x * blockDim.x + threadIdx.x;
    if (threadIdx.x < DIMS) xi[threadIdx.x] = x[(size_t)i * DIMS + threadIdx.x];
    __syncthreads();
    if (j >= NPTS || j < i) return;
    if (i == j) {
        g_d2[(size_t)i * NPTS + j] = dinf();
        return;
    }
    const float* xj = x + (size_t)j * DIMS;
    double dot = 0.0;
    #pragma unroll 8
    for (int d = 0; d < DIMS; d++) {
        dot = fma((double)xi[d], (double)xj[d], dot);
    }
    double v = g_sq[i] + g_sq[j] - 2.0 * dot;
    if (v < 0.0) v = 0.0;
    g_d2[(size_t)i * NPTS + j] = v;
    g_d2[(size_t)j * NPTS + i] = v;
}

// ---------------------------------------------------------------------------
// Round kernel 1: nearest neighbor of every active cluster.
// fp64 bits compared as int64 (all values >= 0 or +inf -> order-preserving).
// ---------------------------------------------------------------------------
__global__ void k_nn() {
    __shared__ long long sv[256];
    __shared__ int       sc[256];
    const int na = g_na;
    if (na <= 1) return;
    const int t = threadIdx.x;
    for (int ridx = blockIdx.x; ridx < na; ridx += gridDim.x) {
        const int a = g_alist[ridx];
        const double* row = g_d2 + (size_t)a * NPTS;
        long long bv = 0x7ff0000000000000LL;  // +inf bits
        int bc = NPTS;
        for (int c = t; c < na; c += 256) {
            const int id = g_alist[c];
            const long long v = __double_as_longlong(row[id]);
            if (v < bv || (v == bv && id < bc)) { bv = v; bc = id; }
        }
        sv[t] = bv; sc[t] = bc;
        __syncthreads();
        for (int s = 128; s > 0; s >>= 1) {
            if (t < s) {
                long long v2 = sv[t + s]; int c2 = sc[t + s];
                if (v2 < sv[t] || (v2 == sv[t] && c2 < sc[t])) {
                    sv[t] = v2; sc[t] = c2;
                }
            }
            __syncthreads();
        }
        if (t == 0) { g_nn[a] = sc[0]; g_nnd[a] = __longlong_as_double(sv[0]); }
        __syncthreads();
    }
}

// ---------------------------------------------------------------------------
// Round kernel 2: detect mutual-NN pairs, log merges, mark flags.
// ---------------------------------------------------------------------------
__global__ void k_pairs() {
    const int na = g_na;
    if (na <= 1) return;
    for (int idx = threadIdx.x; idx < na; idx += 1024) {
        const int a = g_alist[idx];
        const int b = g_nn[a];
        if (a < b && g_nn[b] == a) {
            const int p = atomicAdd(&g_npairs, 1);
            g_pia[p] = a; g_pja[p] = b;
            g_pdij[p] = g_nnd[a];
            g_psi[p] = g_sizes_i[a];
            g_psj[p] = g_sizes_i[b];
            g_flag[a] = 1; g_flag[b] = 1;
            g_dead[b] = 1;
            g_parent[b] = a;
            const int m = atomicAdd(&g_mcnt, 1);
            g_md[m] = g_nnd[a]; g_mj[m] = b;
        }
    }
}

// ---------------------------------------------------------------------------
// Round kernel 3: Lance-Williams update of every pair row vs every
// non-merged active cluster (bit-exact to greedy; reference expression).
// ---------------------------------------------------------------------------
__global__ void k_update() {
    const int na = g_na;
    if (na <= 1) return;
    const int np = g_npairs;
    const long long total = (long long)np * na;
    const long long stride = (long long)gridDim.x * blockDim.x;
    for (long long w = (long long)blockIdx.x * blockDim.x + threadIdx.x;
         w < total; w += stride) {
        const int p = (int)(w / na);
        const int idx = (int)(w - (long long)p * na);
        const int m = g_alist[idx];
        if (g_flag[m]) continue;
        const int iA = g_pia[p], jA = g_pja[p];
        const double si = (double)g_psi[p], sj = (double)g_psj[p];
        const double dij = g_pdij[p];
        const double sm = (double)g_sizes_i[m];
        const double a = g_d2[(size_t)iA * NPTS + m];
        const double b = g_d2[(size_t)jA * NPTS + m];
        const double nd = ((si + sm) * a + (sj + sm) * b - sm * dij) / (si + sj + sm);
        g_d2[(size_t)iA * NPTS + m] = nd;
        g_d2[(size_t)m * NPTS + iA] = nd;
    }
}

// ---------------------------------------------------------------------------
// Round kernel 4: cross terms between pairs merged in the same round.
// Applies the two LW updates in greedy order (smaller dij first).
// ---------------------------------------------------------------------------
__global__ void k_cross() {
    const int np = g_npairs;
    if (np < 2) return;
    const long long total = (long long)np * np;
    const long long stride = (long long)gridDim.x * blockDim.x;
    for (long long w = (long long)blockIdx.x * blockDim.x + threadIdx.x;
         w < total; w += stride) {
        const int p = (int)(w / np);
        const int q = (int)(w - (long long)p * np);
        if (p >= q) continue;
        // earlier pair E = smaller dij (greedy merge order among the round's pairs)
        const double dp = g_pdij[p], dq = g_pdij[q];
        int e, l;
        if (dp < dq || (dp == dq && g_pia[p] < g_pia[q])) { e = p; l = q; }
        else                                              { e = q; l = p; }
        const int iE = g_pia[e], jE = g_pja[e];
        const int iL = g_pia[l], jL = g_pja[l];
        const double siE = (double)g_psi[e], sjE = (double)g_psj[e], dE = g_pdij[e];
        const double siL = (double)g_psi[l], sjL = (double)g_psj[l], dL = g_pdij[l];
        // E's merge updates entries (iE', iL) and (iE', jL):
        const double a1 = g_d2[(size_t)iE * NPTS + iL];
        const double b1 = g_d2[(size_t)jE * NPTS + iL];
        const double u  = ((siE + siL) * a1 + (sjE + siL) * b1 - siL * dE) / (siE + sjE + siL);
        const double a2 = g_d2[(size_t)iE * NPTS + jL];
        const double b2 = g_d2[(size_t)jE * NPTS + jL];
        const double v  = ((siE + sjL) * a2 + (sjE + sjL) * b2 - sjL * dE) / (siE + sjE + sjL);
        // L's merge: m = E-cluster with size siE+sjE
        const double smE = siE + sjE;
        const double nd  = ((siL + smE) * u + (sjL + smE) * v - smE * dL) / (siL + sjL + smE);
        g_d2[(size_t)iE * NPTS + iL] = nd;
        g_d2[(size_t)iL * NPTS + iE] = nd;
    }
}

// ---------------------------------------------------------------------------
// Round kernel 5: sizes update, stable compaction of the active list,
// flag clear, pair-count reset.
// ---------------------------------------------------------------------------
__global__ void k_post() {
    __shared__ int s_id[NPTS];
    __shared__ unsigned char s_kp[NPTS];
    __shared__ int s_a[1024], s_b[1024];
    const int t = threadIdx.x;
    const int na = g_na;
    const int np = g_npairs;
    if (na > 1) {
        // sizes
        for (int p = t; p < np; p += 1024) g_sizes_i[g_pia[p]] += g_psj[p];
        // load + keep flags (thread t owns contiguous elements 2t, 2t+1)
        const int i0 = 2 * t, i1 = 2 * t + 1;
        int c = 0;
        if (i0 < na) { s_id[i0] = g_alist[i0]; s_kp[i0] = !g_dead[s_id[i0]]; c += s_kp[i0]; }
        if (i1 < na) { s_id[i1] = g_alist[i1]; s_kp[i1] = !g_dead[s_id[i1]]; c += s_kp[i1]; }
        s_a[t] = c;
        __syncthreads();
        // Hillis-Steele inclusive scan over 1024 thread counts (ping-pong)
        int* src = s_a; int* dst = s_b;
        for (int off = 1; off < 1024; off <<= 1) {
            int v = src[t];
            if (t >= off) v += src[t - off];
            dst[t] = v;
            __syncthreads();
            int* tmp = src; src = dst; dst = tmp;
        }
        int pos = (t > 0) ? src[t - 1] : 0;
        if (i0 < na && s_kp[i0]) g_alist[pos++] = s_id[i0];
        if (i1 < na && s_kp[i1]) g_alist[pos]   = s_id[i1];
        __syncthreads();
        if (t == 0) { g_na = src[1023]; g_npairs = 0; }
    }
    // clear round flags
    g_flag[t] = 0;
    g_flag[t + 1024] = 0;
}

// ---------------------------------------------------------------------------
// Bitonic sort of all merge heights; theta = (NPTS-K)-th smallest.
// ---------------------------------------------------------------------------
__global__ void k_sortcut(int K) {
    __shared__ double s_d[NPTS];
    const int t = threadIdx.x;
    const int mc = g_mcnt;
    for (int i = t; i < NPTS; i += 1024) s_d[i] = (i < mc) ? g_md[i] : dinf();
    __syncthreads();
    for (int k2 = 2; k2 <= NPTS; k2 <<= 1) {
        for (int j = k2 >> 1; j > 0; j >>= 1) {
            for (int i = t; i < NPTS; i += 1024) {
                const int ixj = i ^ j;
                if (ixj > i) {
                    const bool up = ((i & k2) == 0);
                    const double a = s_d[i], b = s_d[ixj];
                    if (up ? (a > b) : (a < b)) { s_d[i] = b; s_d[ixj] = a; }
                }
            }
            __syncthreads();
        }
    }
    if (t == 0) g_theta = s_d[NPTS - K - 1];
}

// Mark survivors: clear g_active for the child of every kept merge.
__global__ void k_mark() {
    const int i = blockIdx.x * blockDim.x + threadIdx.x;
    if (i < g_mcnt && g_md[i] <= g_theta) g_active[g_mj[i]] = 0;
}

// ---------------------------------------------------------------------------
// Relabel: walk kept-merge parent chain to surviving representative
// (= min point index in cluster); label = rank among sorted survivors.
// ---------------------------------------------------------------------------
__global__ void k_finalize() {
    int p = blockIdx.x * blockDim.x + threadIdx.x;
    if (p >= NPTS) return;
    int c = p;
    while (!g_active[c]) c = g_parent[c];
    int rank = 0;
    for (int q = 0; q < c; q++) rank += g_active[q];
    g_labels[p] = rank;
}

__global__ void k_writeout(float* __restrict__ out, int K) {
    int idx = blockIdx.x * blockDim.x + threadIdx.x;
    int total = NPTS * K;
    if (idx >= total) return;
    int p = idx / K;
    int c = idx - p * K;
    out[idx] = (g_labels[p] == c) ? 1.0f : 0.0f;
}

// ---------------------------------------------------------------------------
extern "C" void kernel_launch(void* const* d_in, const int* in_sizes, int n_in,
                              void* d_out, int out_size) {
    const float* x = (const float*)d_in[0];
    int K = out_size / NPTS;   // out = [B*N, K] one-hot => K from out_size

    k_init_sq<<<(NPTS + 255) / 256, 256>>>(x);
    k_init_d2<<<dim3(NPTS / 128, NPTS), 128>>>(x);

    for (int r = 0; r < ROUNDS; r++) {
        k_nn<<<256, 256>>>();
        k_pairs<<<1, 1024>>>();
        k_update<<<1024, 256>>>();
        k_cross<<<512, 256>>>();
        k_post<<<1, 1024>>>();
    }

    k_sortcut<<<1, 1024>>>(K);
    k_mark<<<(NPTS + 1023) / 1024, 1024>>>();
    k_finalize<<<(NPTS + 255) / 256, 256>>>();
    k_writeout<<<(NPTS * K + 255) / 256, 256>>>((float*)d_out, K);
}

// round 7
// speedup vs baseline: 11.3370x; 1.1818x over previous
#include <cuda_runtime.h>
#include <cuda_bf16.h>
#include <cstdint>

#define NPTS 2048
#define DIMS 96
#define NTH 1024

// Device scratch (no runtime allocation allowed)
__device__ double g_d2[(size_t)NPTS * NPTS];      // 32 MB
__device__ double g_sq[NPTS];
__device__ int    g_alist[NPTS];
__device__ int    g_na;
__device__ int    g_sizes_i[NPTS];
__device__ int    g_nn[NPTS];
__device__ double g_nnd[NPTS];
__device__ unsigned char g_dead[NPTS];
__device__ int    g_parent[NPTS];
__device__ int    g_active[NPTS];
__device__ int    g_rank[NPTS];
__device__ double g_md[NPTS];
__device__ int    g_mj[NPTS];
__device__ int    g_mcnt;
__device__ unsigned g_arrive;
__device__ volatile unsigned g_release;

__device__ __forceinline__ double dinf() {
    return __longlong_as_double(0x7ff0000000000000LL);
}

// sense-reversal software grid barrier (all blocks co-resident by construction)
__device__ __forceinline__ void grid_bar() {
    __syncthreads();
    if (threadIdx.x == 0) {
        __threadfence();
        unsigned gen = g_release;
        if (atomicAdd(&g_arrive, 1) == gridDim.x - 1) {
            atomicExch(&g_arrive, 0);
            __threadfence();
            g_release = gen + 1;
        } else {
            while (g_release == gen) { __nanosleep(32); }
        }
        __threadfence();
    }
    __syncthreads();
}

// ---------------------------------------------------------------------------
__global__ void k_init_sq(const float* __restrict__ x) {
    int i = blockIdx.x * blockDim.x + threadIdx.x;
    if (i >= NPTS) return;
    const float* xr = x + (size_t)i * DIMS;
    double acc = 0.0;
    #pragma unroll 8
    for (int d = 0; d < DIMS; d++) {
        double v = (double)xr[d];
        acc = fma(v, v, acc);
    }
    g_sq[i] = acc;
    g_alist[i] = i;
    g_sizes_i[i] = 1;
    g_parent[i] = i;
    g_active[i] = 1;
    g_dead[i] = 0;
    if (i == 0) { g_na = NPTS; g_mcnt = 0; g_arrive = 0; g_release = 0; }
}

__global__ void k_init_d2(const float* __restrict__ x) {
    __shared__ float xi[DIMS];
    int i = blockIdx.y;
    int j = blockIdx.x * blockDim.x + threadIdx.x;
    if (threadIdx.x < DIMS) xi[threadIdx.x] = x[(size_t)i * DIMS + threadIdx.x];
    __syncthreads();
    if (j >= NPTS || j < i) return;
    if (i == j) {
        g_d2[(size_t)i * NPTS + j] = dinf();
        return;
    }
    const float* xj = x + (size_t)j * DIMS;
    double dot = 0.0;
    #pragma unroll 8
    for (int d = 0; d < DIMS; d++) {
        dot = fma((double)xi[d], (double)xj[d], dot);
    }
    double v = g_sq[i] + g_sq[j] - 2.0 * dot;
    if (v < 0.0) v = 0.0;
    g_d2[(size_t)i * NPTS + j] = v;
    g_d2[(size_t)j * NPTS + i] = v;
}

// ---------------------------------------------------------------------------
// Persistent RNN-rounds kernel: all merge rounds + cut + labels + writeout.
// ---------------------------------------------------------------------------
__global__ void __launch_bounds__(NTH, 1) k_rnn(float* __restrict__ out, int K) {
    __shared__ short s_pia[NPTS / 2], s_pja[NPTS / 2];   // pair list (redundant/block)
    __shared__ int   s_wcnt[64], s_woff[64];
    __shared__ short s_id[NPTS];
    __shared__ unsigned char s_mg[NPTS];                 // merged-this-round / keep flags
    __shared__ int   s_a[NTH], s_b[NTH];
    __shared__ double s_d[NPTS];                         // sort buffer (16 KB)
    __shared__ int   s_np;

    const int t = threadIdx.x;
    const int w = t >> 5, lane = t & 31;
    const int gtid = blockIdx.x * NTH + t;
    const int gstride = gridDim.x * NTH;
    const int gwarp = blockIdx.x * 32 + w;
    const int nwarps = gridDim.x * 32;

    while (true) {
        const int na = *(volatile int*)&g_na;
        if (na <= 1) break;

        // ---- Phase 1: NN of every active cluster (warp per row) ----
        for (int r = gwarp; r < na; r += nwarps) {
            const int a = g_alist[r];
            const double* row = g_d2 + (size_t)a * NPTS;
            long long bv = 0x7ff0000000000000LL; int bc = NPTS;
            for (int c = lane; c < na; c += 32) {
                const int id = g_alist[c];
                const long long v = __double_as_longlong(row[id]);
                if (v < bv || (v == bv && id < bc)) { bv = v; bc = id; }
            }
            #pragma unroll
            for (int o = 16; o > 0; o >>= 1) {
                long long ov = __shfl_down_sync(0xffffffffu, bv, o);
                int       oc = __shfl_down_sync(0xffffffffu, bc, o);
                if (ov < bv || (ov == bv && oc < bc)) { bv = ov; bc = oc; }
            }
            if (lane == 0) { g_nn[a] = bc; g_nnd[a] = __longlong_as_double(bv); }
        }
        grid_bar();

        // ---- Phase 2a: redundant deterministic pair detection (every block) ----
        bool p0 = false, p1 = false;
        int a0 = 0, b0 = 0, a1 = 0, b1 = 0;
        if (t < na) {
            a0 = g_alist[t]; b0 = g_nn[a0];
            p0 = (a0 < b0) && (g_nn[b0] == a0);
            s_mg[t] = (unsigned char)(g_nn[b0] == a0);      // t's cluster merged?
        }
        const int t2 = t + NTH;
        if (t2 < na) {
            a1 = g_alist[t2]; b1 = g_nn[a1];
            p1 = (a1 < b1) && (g_nn[b1] == a1);
            s_mg[t2] = (unsigned char)(g_nn[b1] == a1);
        }
        const unsigned m0 = __ballot_sync(0xffffffffu, p0);
        const unsigned m1 = __ballot_sync(0xffffffffu, p1);
        if (lane == 0) { s_wcnt[w] = __popc(m0); s_wcnt[32 + w] = __popc(m1); }
        __syncthreads();
        if (t == 0) {
            int acc = 0;
            #pragma unroll
            for (int q = 0; q < 64; q++) { s_woff[q] = acc; acc += s_wcnt[q]; }
            s_np = acc;
        }
        __syncthreads();
        if (p0) {
            const int pos = s_woff[w] + __popc(m0 & ((1u << lane) - 1u));
            s_pia[pos] = (short)a0; s_pja[pos] = (short)b0;
        }
        if (p1) {
            const int pos = s_woff[32 + w] + __popc(m1 & ((1u << lane) - 1u));
            s_pia[pos] = (short)a1; s_pja[pos] = (short)b1;
        }
        __syncthreads();
        const int np = s_np;

        if (blockIdx.x == 0) {           // merge-log + parent/dead side effects
            const int mbase = g_mcnt;
            for (int p = t; p < np; p += NTH) {
                const int ia = (int)s_pia[p], ja = (int)s_pja[p];
                g_parent[ja] = ia;
                g_dead[ja] = 1;
                g_md[mbase + p] = g_nnd[ia];
                g_mj[mbase + p] = ja;
            }
            if (t == 0) g_mcnt = mbase + np;
        }

        // ---- Phase 2b: Lance-Williams updates (pair x unmerged active) ----
        const long long tot1 = (long long)np * na;
        for (long long xw = gtid; xw < tot1; xw += gstride) {
            const int p = (int)(xw / na);
            const int idx = (int)(xw - (long long)p * na);
            if (s_mg[idx]) continue;
            const int m = g_alist[idx];
            const int iA = (int)s_pia[p], jA = (int)s_pja[p];
            const double si = (double)g_sizes_i[iA], sj = (double)g_sizes_i[jA];
            const double dij = g_nnd[iA];
            const double sm = (double)g_sizes_i[m];
            const double a = g_d2[(size_t)iA * NPTS + m];
            const double b = g_d2[(size_t)jA * NPTS + m];
            const double nd = ((si + sm) * a + (sj + sm) * b - sm * dij) / (si + sj + sm);
            g_d2[(size_t)iA * NPTS + m] = nd;
            g_d2[(size_t)m * NPTS + iA] = nd;
        }
        // ---- cross terms between same-round pairs (greedy order by dij) ----
        const long long tot2 = (long long)np * np;
        for (long long xw = gtid; xw < tot2; xw += gstride) {
            const int p = (int)(xw / np);
            const int q = (int)(xw - (long long)p * np);
            if (p >= q) continue;
            const double dp = g_nnd[(int)s_pia[p]], dq = g_nnd[(int)s_pia[q]];
            int e, l;
            if (dp < dq || (dp == dq && s_pia[p] < s_pia[q])) { e = p; l = q; }
            else                                              { e = q; l = p; }
            const int iE = (int)s_pia[e], jE = (int)s_pja[e];
            const int iL = (int)s_pia[l], jL = (int)s_pja[l];
            const double siE = (double)g_sizes_i[iE], sjE = (double)g_sizes_i[jE];
            const double dE = g_nnd[iE];
            const double siL = (double)g_sizes_i[iL], sjL = (double)g_sizes_i[jL];
            const double dL = g_nnd[iL];
            const double a1c = g_d2[(size_t)iE * NPTS + iL];
            const double b1c = g_d2[(size_t)jE * NPTS + iL];
            const double u = ((siE + siL) * a1c + (sjE + siL) * b1c - siL * dE) / (siE + sjE + siL);
            const double a2c = g_d2[(size_t)iE * NPTS + jL];
            const double b2c = g_d2[(size_t)jE * NPTS + jL];
            const double v = ((siE + sjL) * a2c + (sjE + sjL) * b2c - sjL * dE) / (siE + sjE + sjL);
            const double smE = siE + sjE;
            const double nd = ((siL + smE) * u + (sjL + smE) * v - smE * dL) / (siL + sjL + smE);
            g_d2[(size_t)iE * NPTS + iL] = nd;
            g_d2[(size_t)iL * NPTS + iE] = nd;
        }
        grid_bar();

        // ---- Phase 3: post (block 0): sizes, stable compaction of alist ----
        if (blockIdx.x == 0) {
            for (int p = t; p < np; p += NTH)
                g_sizes_i[(int)s_pia[p]] += g_sizes_i[(int)s_pja[p]];
            const int i0 = 2 * t, i1 = 2 * t + 1;
            int c = 0;
            unsigned char k0 = 0, k1 = 0;
            if (i0 < na) { s_id[i0] = (short)g_alist[i0]; k0 = !g_dead[(int)s_id[i0]]; c += k0; }
            if (i1 < na) { s_id[i1] = (short)g_alist[i1]; k1 = !g_dead[(int)s_id[i1]]; c += k1; }
            s_a[t] = c;
            __syncthreads();
            int* src = s_a; int* dst = s_b;
            for (int off = 1; off < NTH; off <<= 1) {
                int v = src[t];
                if (t >= off) v += src[t - off];
                dst[t] = v;
                __syncthreads();
                int* tmp = src; src = dst; dst = tmp;
            }
            int pos = (t > 0) ? src[t - 1] : 0;
            if (i0 < na && k0) g_alist[pos++] = (int)s_id[i0];
            if (i1 < na && k1) g_alist[pos] = (int)s_id[i1];
            __syncthreads();
            if (t == 0) g_na = src[NTH - 1];
        }
        grid_bar();
    }

    // ---- Tail: sort merge heights, cut, mark, ranks (block 0) ----
    if (blockIdx.x == 0) {
        const int mc = g_mcnt;
        for (int i = t; i < NPTS; i += NTH) s_d[i] = (i < mc) ? g_md[i] : dinf();
        __syncthreads();
        for (int k2 = 2; k2 <= NPTS; k2 <<= 1) {
            for (int jj = k2 >> 1; jj > 0; jj >>= 1) {
                for (int i = t; i < NPTS; i += NTH) {
                    const int ixj = i ^ jj;
                    if (ixj > i) {
                        const bool up = ((i & k2) == 0);
                        const double aa = s_d[i], bb = s_d[ixj];
                        if (up ? (aa > bb) : (aa < bb)) { s_d[i] = bb; s_d[ixj] = aa; }
                    }
                }
                __syncthreads();
            }
        }
        const double theta = s_d[NPTS - K - 1];
        for (int i = t; i < mc; i += NTH)
            if (g_md[i] <= theta) g_active[g_mj[i]] = 0;
        __syncthreads();
        // ranks: exclusive prefix over g_active (parallel scan)
        const int e0 = g_active[2 * t], e1 = g_active[2 * t + 1];
        s_a[t] = e0 + e1;
        __syncthreads();
        int* src = s_a; int* dst = s_b;
        for (int off = 1; off < NTH; off <<= 1) {
            int v = src[t];
            if (t >= off) v += src[t - off];
            dst[t] = v;
            __syncthreads();
            int* tmp = src; src = dst; dst = tmp;
        }
        const int base = (t > 0) ? src[t - 1] : 0;
        g_rank[2 * t] = base;
        g_rank[2 * t + 1] = base + e0;
    }
    grid_bar();

    // ---- labels + one-hot writeout (all blocks) ----
    for (int p = gtid; p < NPTS; p += gstride) {
        int c = p;
        while (!g_active[c]) c = g_parent[c];
        const int lab = g_rank[c];
        float* o = out + (size_t)p * K;
        for (int q = 0; q < K; q++) o[q] = (q == lab) ? 1.0f : 0.0f;
    }
}

// ---------------------------------------------------------------------------
extern "C" void kernel_launch(void* const* d_in, const int* in_sizes, int n_in,
                              void* d_out, int out_size) {
    const float* x = (const float*)d_in[0];
    int K = out_size / NPTS;   // out = [B*N, K] one-hot => K from out_size

    static int nsm = 0;
    if (nsm == 0) {
        int v = 0;
        if (cudaDeviceGetAttribute(&v, cudaDevAttrMultiProcessorCount, 0) == cudaSuccess && v > 0)
            nsm = v;
        else
            nsm = 64;   // conservative fallback: fewer blocks than any plausible SM count
    }

    k_init_sq<<<(NPTS + 255) / 256, 256>>>(x);
    k_init_d2<<<dim3(NPTS / 128, NPTS), 128>>>(x);
    k_rnn<<<nsm, NTH>>>((float*)d_out, K);
}

// round 8
// speedup vs baseline: 16.3067x; 1.4384x over previous
#include <cuda_runtime.h>
#include <cuda_bf16.h>
#include <cstdint>

#define NPTS 2048
#define DIMS 96
#define NTH 1024
#define GRID 64
#define THRESH 512
#define MAXP 1024
#define TILE 32

// Device scratch (no runtime allocation allowed)
__device__ double g_d2[(size_t)NPTS * NPTS];      // 32 MB
__device__ double g_sq[NPTS];
__device__ int    g_nn[NPTS];
__device__ double g_nnd[NPTS];
__device__ int    g_parent[NPTS];
__device__ int    g_active[NPTS];
__device__ int    g_rank[NPTS];
__device__ double g_md[NPTS];
__device__ int    g_mj[NPTS];
__device__ int    g_mcnt;
__device__ unsigned g_arrive;
__device__ volatile unsigned g_release;

__device__ __forceinline__ double dinf() {
    return __longlong_as_double(0x7ff0000000000000LL);
}

// sense-reversal software grid barrier (all blocks co-resident by construction)
__device__ __forceinline__ void grid_bar() {
    __syncthreads();
    if (threadIdx.x == 0) {
        __threadfence();
        unsigned gen = g_release;
        if (atomicAdd(&g_arrive, 1) == gridDim.x - 1) {
            atomicExch(&g_arrive, 0);
            __threadfence();
            g_release = gen + 1;
        } else {
            while (g_release == gen) { __nanosleep(32); }
        }
        __threadfence();
    }
    __syncthreads();
}

// ---------------------------------------------------------------------------
__global__ void k_init_sq(const float* __restrict__ x) {
    int i = blockIdx.x * blockDim.x + threadIdx.x;
    if (i >= NPTS) return;
    const float* xr = x + (size_t)i * DIMS;
    double acc = 0.0;
    #pragma unroll 8
    for (int d = 0; d < DIMS; d++) {
        double v = (double)xr[d];
        acc = fma(v, v, acc);
    }
    g_sq[i] = acc;
    g_parent[i] = i;
    g_active[i] = 1;
    if (i == 0) { g_mcnt = 0; g_arrive = 0; g_release = 0; }
}

// ---------------------------------------------------------------------------
// Tiled fp64 distance matrix: 32x32 upper-triangular tiles, x staged in
// padded smem; per-element serial-fma arithmetic identical to prior rounds.
// ---------------------------------------------------------------------------
__global__ void k_init_d2(const float* __restrict__ x) {
    __shared__ float A[TILE][DIMS + 1];
    __shared__ float B[TILE][DIMS + 1];
    const int ti = blockIdx.y, tj = blockIdx.x;
    if (tj < ti) return;
    for (int idx = threadIdx.x; idx < TILE * DIMS; idx += blockDim.x) {
        const int r = idx / DIMS, d = idx - r * DIMS;
        A[r][d] = x[(size_t)(ti * TILE + r) * DIMS + d];
        B[r][d] = x[(size_t)(tj * TILE + r) * DIMS + d];
    }
    __syncthreads();
    #pragma unroll
    for (int e = 0; e < (TILE * TILE) / 256; e++) {
        const int idx = threadIdx.x + e * 256;
        const int r = idx >> 5, c = idx & 31;
        const int gi = ti * TILE + r, gj = tj * TILE + c;
        if (gj < gi) continue;
        if (gi == gj) { g_d2[(size_t)gi * NPTS + gj] = dinf(); continue; }
        double dot = 0.0;
        #pragma unroll 8
        for (int d = 0; d < DIMS; d++) {
            dot = fma((double)A[r][d], (double)B[c][d], dot);
        }
        double v = g_sq[gi] + g_sq[gj] - 2.0 * dot;
        if (v < 0.0) v = 0.0;
        g_d2[(size_t)gi * NPTS + gj] = v;
        g_d2[(size_t)gj * NPTS + gi] = v;
    }
}

// ---------------------------------------------------------------------------
// Persistent RNN-rounds kernel with block-local replicated cluster state.
// ---------------------------------------------------------------------------
__global__ void __launch_bounds__(NTH, 1) k_rnn(float* __restrict__ out, int K) {
    __shared__ short s_alist[NPTS];                  // 4 KB (block-local, replicated)
    __shared__ unsigned short s_sizes[NPTS];         // 4 KB (block-local, replicated)
    __shared__ short s_pia[MAXP], s_pja[MAXP];       // 4 KB
    __shared__ unsigned char s_mg[NPTS];             // 2 KB
    __shared__ short s_id[NPTS];                     // 4 KB
    __shared__ int   s_a[NTH], s_b[NTH];             // 8 KB
    __shared__ double s_d[NPTS];                     // 16 KB (tail sort only)
    __shared__ int   s_wcnt[64], s_woff[64];
    __shared__ int   s_np, s_na;

    const int t = threadIdx.x;
    const int w = t >> 5, lane = t & 31;
    const int gtid = blockIdx.x * NTH + t;
    const int gstride = gridDim.x * NTH;
    const int gwarp = blockIdx.x * 32 + w;
    const int nwarps = gridDim.x * 32;

    for (int r = t; r < NPTS; r += NTH) { s_alist[r] = (short)r; s_sizes[r] = 1; }
    if (t == 0) s_na = NPTS;
    __syncthreads();

    // ---- NN of active clusters: warp per row, alist from LDS ----
    auto nn_phase = [&](int firstRow, int rowStride, int na) {
        for (int r = firstRow; r < na; r += rowStride) {
            const int a = (int)s_alist[r];
            const double* row = g_d2 + (size_t)a * NPTS;
            long long bv = 0x7ff0000000000000LL; int bc = NPTS;
            for (int c = lane; c < na; c += 32) {
                const int id = (int)s_alist[c];
                const long long v = __double_as_longlong(row[id]);
                if (v < bv || (v == bv && id < bc)) { bv = v; bc = id; }
            }
            #pragma unroll
            for (int o = 16; o > 0; o >>= 1) {
                long long ov = __shfl_down_sync(0xffffffffu, bv, o);
                int       oc = __shfl_down_sync(0xffffffffu, bc, o);
                if (ov < bv || (ov == bv && oc < bc)) { bv = ov; bc = oc; }
            }
            if (lane == 0) { g_nn[a] = bc; g_nnd[a] = __longlong_as_double(bv); }
        }
    };

    // ---- deterministic pair detection into s_pia/s_pja (per block) ----
    auto pairs_phase = [&](int na) {
        bool p0 = false, p1 = false;
        int a0 = 0, b0 = 0, a1 = 0, b1 = 0;
        if (t < na) {
            a0 = (int)s_alist[t]; b0 = g_nn[a0];
            const bool mut = (g_nn[b0] == a0);
            p0 = mut && (a0 < b0);
            s_mg[t] = (unsigned char)mut;
        }
        const int t2 = t + NTH;
        if (t2 < na) {
            a1 = (int)s_alist[t2]; b1 = g_nn[a1];
            const bool mut = (g_nn[b1] == a1);
            p1 = mut && (a1 < b1);
            s_mg[t2] = (unsigned char)mut;
        }
        const unsigned m0 = __ballot_sync(0xffffffffu, p0);
        const unsigned m1 = __ballot_sync(0xffffffffu, p1);
        if (lane == 0) { s_wcnt[w] = __popc(m0); s_wcnt[32 + w] = __popc(m1); }
        __syncthreads();
        if (t == 0) {
            int acc = 0;
            #pragma unroll
            for (int q = 0; q < 64; q++) { s_woff[q] = acc; acc += s_wcnt[q]; }
            s_np = acc;
        }
        __syncthreads();
        if (p0) {
            const int pos = s_woff[w] + __popc(m0 & ((1u << lane) - 1u));
            s_pia[pos] = (short)a0; s_pja[pos] = (short)b0;
        }
        if (p1) {
            const int pos = s_woff[32 + w] + __popc(m1 & ((1u << lane) - 1u));
            s_pia[pos] = (short)a1; s_pja[pos] = (short)b1;
        }
        __syncthreads();
    };

    // ---- merge log + parent (only meaningful on block 0) ----
    auto log_phase = [&](int np) {
        const int mbase = g_mcnt;
        for (int p = t; p < np; p += NTH) {
            const int ia = (int)s_pia[p], ja = (int)s_pja[p];
            g_parent[ja] = ia;
            g_md[mbase + p] = g_nnd[ia];
            g_mj[mbase + p] = ja;
        }
        __syncthreads();
        if (t == 0) g_mcnt = mbase + np;
    };

    // ---- Lance-Williams updates: (pair x unmerged) + same-round cross ----
    auto lw_phase = [&](int na, int np, long long start, long long stride) {
        const long long tot1 = (long long)np * na;
        for (long long xw = start; xw < tot1; xw += stride) {
            const int p = (int)(xw / na);
            const int idx = (int)(xw - (long long)p * na);
            if (s_mg[idx]) continue;
            const int m = (int)s_alist[idx];
            const int iA = (int)s_pia[p], jA = (int)s_pja[p];
            const double si = (double)s_sizes[iA], sj = (double)s_sizes[jA];
            const double dij = g_nnd[iA];
            const double sm = (double)s_sizes[m];
            const double a = g_d2[(size_t)iA * NPTS + m];
            const double b = g_d2[(size_t)jA * NPTS + m];
            const double nd = ((si + sm) * a + (sj + sm) * b - sm * dij) / (si + sj + sm);
            g_d2[(size_t)iA * NPTS + m] = nd;
            g_d2[(size_t)m * NPTS + iA] = nd;
        }
        const long long tot2 = (long long)np * np;
        for (long long xw = start; xw < tot2; xw += stride) {
            const int p = (int)(xw / np);
            const int q = (int)(xw - (long long)p * np);
            if (p >= q) continue;
            const double dp = g_nnd[(int)s_pia[p]], dq = g_nnd[(int)s_pia[q]];
            int e, l;
            if (dp < dq || (dp == dq && s_pia[p] < s_pia[q])) { e = p; l = q; }
            else                                              { e = q; l = p; }
            const int iE = (int)s_pia[e], jE = (int)s_pja[e];
            const int iL = (int)s_pia[l], jL = (int)s_pja[l];
            const double siE = (double)s_sizes[iE], sjE = (double)s_sizes[jE];
            const double dE = g_nnd[iE];
            const double siL = (double)s_sizes[iL], sjL = (double)s_sizes[jL];
            const double dL = g_nnd[iL];
            const double a1c = g_d2[(size_t)iE * NPTS + iL];
            const double b1c = g_d2[(size_t)jE * NPTS + iL];
            const double u = ((siE + siL) * a1c + (sjE + siL) * b1c - siL * dE) / (siE + sjE + siL);
            const double a2c = g_d2[(size_t)iE * NPTS + jL];
            const double b2c = g_d2[(size_t)jE * NPTS + jL];
            const double v = ((siE + sjL) * a2c + (sjE + sjL) * b2c - sjL * dE) / (siE + sjE + sjL);
            const double smE = siE + sjE;
            const double nd = ((siL + smE) * u + (sjL + smE) * v - smE * dL) / (siL + sjL + smE);
            g_d2[(size_t)iE * NPTS + iL] = nd;
            g_d2[(size_t)iL * NPTS + iE] = nd;
        }
    };

    // ---- block-local sizes update + stable alist compaction ----
    auto post_phase = [&](int na, int np) {
        for (int p = t; p < np; p += NTH)
            s_sizes[(int)s_pia[p]] = (unsigned short)(s_sizes[(int)s_pia[p]] + s_sizes[(int)s_pja[p]]);
        const int i0 = 2 * t, i1 = 2 * t + 1;
        int c = 0;
        unsigned char k0 = 0, k1 = 0;
        if (i0 < na) {
            const int a = (int)s_alist[i0]; s_id[i0] = (short)a;
            const int b = g_nn[a];
            k0 = !((g_nn[b] == a) && (b < a));   // dead iff merged as j
            c += k0;
        }
        if (i1 < na) {
            const int a = (int)s_alist[i1]; s_id[i1] = (short)a;
            const int b = g_nn[a];
            k1 = !((g_nn[b] == a) && (b < a));
            c += k1;
        }
        s_a[t] = c;
        __syncthreads();
        int* src = s_a; int* dst = s_b;
        for (int off = 1; off < NTH; off <<= 1) {
            int v = src[t];
            if (t >= off) v += src[t - off];
            dst[t] = v;
            __syncthreads();
            int* tmp = src; src = dst; dst = tmp;
        }
        int pos = (t > 0) ? src[t - 1] : 0;
        if (i0 < na && k0) s_alist[pos++] = s_id[i0];
        if (i1 < na && k1) s_alist[pos] = s_id[i1];
        if (t == 0) s_na = src[NTH - 1];
        __syncthreads();
    };

    // ================= grid-wide rounds =================
    while (true) {
        const int na = s_na;
        if (na <= THRESH) break;
        nn_phase(gwarp, nwarps, na);
        grid_bar();
        pairs_phase(na);
        const int np = s_np;
        if (blockIdx.x == 0) log_phase(np);
        lw_phase(na, np, gtid, gstride);
        __syncthreads();
        post_phase(na, np);
        grid_bar();
    }

    // ================= single-block endgame (block 0) =================
    if (blockIdx.x == 0) {
        while (true) {
            const int na = s_na;
            if (na <= 1) break;
            nn_phase(w, 32, na);
            __syncthreads();
            pairs_phase(na);
            const int np = s_np;
            log_phase(np);
            lw_phase(na, np, t, NTH);
            __syncthreads();
            post_phase(na, np);
        }

        // ---- tail: sort merge heights, cut, mark, ranks ----
        const int mc = g_mcnt;
        for (int i = t; i < NPTS; i += NTH) s_d[i] = (i < mc) ? g_md[i] : dinf();
        __syncthreads();
        for (int k2 = 2; k2 <= NPTS; k2 <<= 1) {
            for (int jj = k2 >> 1; jj > 0; jj >>= 1) {
                for (int i = t; i < NPTS; i += NTH) {
                    const int ixj = i ^ jj;
                    if (ixj > i) {
                        const bool up = ((i & k2) == 0);
                        const double aa = s_d[i], bb = s_d[ixj];
                        if (up ? (aa > bb) : (aa < bb)) { s_d[i] = bb; s_d[ixj] = aa; }
                    }
                }
                __syncthreads();
            }
        }
        const double theta = s_d[NPTS - K - 1];
        for (int i = t; i < mc; i += NTH)
            if (g_md[i] <= theta) g_active[g_mj[i]] = 0;
        __syncthreads();
        const int e0 = g_active[2 * t], e1 = g_active[2 * t + 1];
        s_a[t] = e0 + e1;
        __syncthreads();
        int* src = s_a; int* dst = s_b;
        for (int off = 1; off < NTH; off <<= 1) {
            int v = src[t];
            if (t >= off) v += src[t - off];
            dst[t] = v;
            __syncthreads();
            int* tmp = src; src = dst; dst = tmp;
        }
        const int base = (t > 0) ? src[t - 1] : 0;
        g_rank[2 * t] = base;
        g_rank[2 * t + 1] = base + e0;
    }
    grid_bar();

    // ---- labels + one-hot writeout (all blocks) ----
    for (int p = gtid; p < NPTS; p += gstride) {
        int c = p;
        while (!g_active[c]) c = g_parent[c];
        const int lab = g_rank[c];
        float* o = out + (size_t)p * K;
        for (int q = 0; q < K; q++) o[q] = (q == lab) ? 1.0f : 0.0f;
    }
}

// ---------------------------------------------------------------------------
extern "C" void kernel_launch(void* const* d_in, const int* in_sizes, int n_in,
                              void* d_out, int out_size) {
    const float* x = (const float*)d_in[0];
    int K = out_size / NPTS;   // out = [B*N, K] one-hot => K from out_size

    k_init_sq<<<(NPTS + 255) / 256, 256>>>(x);
    k_init_d2<<<dim3(NPTS / TILE, NPTS / TILE), 256>>>(x);
    k_rnn<<<GRID, NTH>>>((float*)d_out, K);
}

// round 9
// speedup vs baseline: 23.1038x; 1.4168x over previous
#include <cuda_runtime.h>
#include <cuda_bf16.h>
#include <cstdint>

#define NPTS 2048
#define DIMS 96
#define NTH 1024
#define THRESH 64
#define MAXP 1024
#define TILE 32
#define RECIPN (NPTS + 1)

// Device scratch (no runtime allocation allowed)
__device__ double g_d2[(size_t)NPTS * NPTS];      // 32 MB
__device__ double g_sq[NPTS];
__device__ double g_recip[RECIPN];
__device__ int    g_nn[NPTS];
__device__ double g_nnd[NPTS];
__device__ int    g_parent[NPTS];
__device__ int    g_active[NPTS];
__device__ int    g_rank[NPTS];
__device__ double g_md[NPTS];
__device__ int    g_mj[NPTS];
__device__ int    g_mcnt;
__device__ unsigned g_arrive;
__device__ volatile unsigned g_release;

__device__ __forceinline__ double dinf() {
    return __longlong_as_double(0x7ff0000000000000LL);
}

// Markstein correctly-rounded division num/T given r = RN(1/T): returns RN(num/T).
__device__ __forceinline__ double div_exact(double num, double T, double r) {
    double q0 = __dmul_rn(num, r);
    double e  = __fma_rn(-T, q0, num);
    return __fma_rn(e, r, q0);
}

// sense-reversal software grid barrier (all blocks co-resident by construction)
__device__ __forceinline__ void grid_bar() {
    __syncthreads();
    if (threadIdx.x == 0) {
        __threadfence();
        unsigned gen = g_release;
        if (atomicAdd(&g_arrive, 1) == gridDim.x - 1) {
            atomicExch(&g_arrive, 0);
            __threadfence();
            g_release = gen + 1;
        } else {
            while (g_release == gen) { __nanosleep(32); }
        }
        __threadfence();
    }
    __syncthreads();
}

// ---------------------------------------------------------------------------
__global__ void k_init_sq(const float* __restrict__ x) {
    int i = blockIdx.x * blockDim.x + threadIdx.x;
    if (i >= NPTS) return;
    g_recip[i + 1] = 1.0 / (double)(i + 1);
    if (i == 0) g_recip[0] = 1.0;
    const float* xr = x + (size_t)i * DIMS;
    double acc = 0.0;
    #pragma unroll 8
    for (int d = 0; d < DIMS; d++) {
        double v = (double)xr[d];
        acc = fma(v, v, acc);
    }
    g_sq[i] = acc;
    g_parent[i] = i;
    g_active[i] = 1;
    if (i == 0) { g_mcnt = 0; g_arrive = 0; g_release = 0; }
}

// ---------------------------------------------------------------------------
// Tiled fp64 distance matrix: 32x32 upper-triangular tiles, x staged in
// padded smem; per-element serial-fma arithmetic identical to prior rounds.
// ---------------------------------------------------------------------------
__global__ void k_init_d2(const float* __restrict__ x) {
    __shared__ float A[TILE][DIMS + 1];
    __shared__ float B[TILE][DIMS + 1];
    const int ti = blockIdx.y, tj = blockIdx.x;
    if (tj < ti) return;
    for (int idx = threadIdx.x; idx < TILE * DIMS; idx += blockDim.x) {
        const int r = idx / DIMS, d = idx - r * DIMS;
        A[r][d] = x[(size_t)(ti * TILE + r) * DIMS + d];
        B[r][d] = x[(size_t)(tj * TILE + r) * DIMS + d];
    }
    __syncthreads();
    #pragma unroll
    for (int e = 0; e < (TILE * TILE) / 256; e++) {
        const int idx = threadIdx.x + e * 256;
        const int r = idx >> 5, c = idx & 31;
        const int gi = ti * TILE + r, gj = tj * TILE + c;
        if (gj < gi) continue;
        if (gi == gj) { g_d2[(size_t)gi * NPTS + gj] = dinf(); continue; }
        double dot = 0.0;
        #pragma unroll 8
        for (int d = 0; d < DIMS; d++) {
            dot = fma((double)A[r][d], (double)B[c][d], dot);
        }
        double v = g_sq[gi] + g_sq[gj] - 2.0 * dot;
        if (v < 0.0) v = 0.0;
        g_d2[(size_t)gi * NPTS + gj] = v;
        g_d2[(size_t)gj * NPTS + gi] = v;
    }
}

// ---------------------------------------------------------------------------
// Persistent RNN-rounds kernel with block-local replicated cluster state.
// ---------------------------------------------------------------------------
__global__ void __launch_bounds__(NTH, 1) k_rnn(float* __restrict__ out, int K) {
    __shared__ short s_alist[NPTS];                  // 4 KB (block-local, replicated)
    __shared__ unsigned short s_sizes[NPTS];         // 4 KB (block-local, replicated)
    __shared__ short s_pia[MAXP], s_pja[MAXP];       // 4 KB
    __shared__ unsigned char s_mg[NPTS];             // 2 KB
    __shared__ short s_id[NPTS];                     // 4 KB
    __shared__ int   s_a[NTH], s_b[NTH];             // 8 KB
    __shared__ double s_d[NPTS];                     // 16 KB (tail sort only)
    __shared__ int   s_wcnt[64], s_woff[64];
    __shared__ int   s_np, s_na;

    const int t = threadIdx.x;
    const int w = t >> 5, lane = t & 31;
    const int gtid = blockIdx.x * NTH + t;
    const int gstride = gridDim.x * NTH;
    const int gwarp = blockIdx.x * 32 + w;
    const int nwarps = gridDim.x * 32;

    for (int r = t; r < NPTS; r += NTH) { s_alist[r] = (short)r; s_sizes[r] = 1; }
    if (t == 0) s_na = NPTS;
    __syncthreads();

    // ---- NN of active clusters: warp per row, alist from LDS ----
    auto nn_phase = [&](int firstRow, int rowStride, int na) {
        for (int r = firstRow; r < na; r += rowStride) {
            const int a = (int)s_alist[r];
            const double* row = g_d2 + (size_t)a * NPTS;
            long long bv = 0x7ff0000000000000LL; int bc = NPTS;
            for (int c = lane; c < na; c += 32) {
                const int id = (int)s_alist[c];
                const long long v = __double_as_longlong(row[id]);
                if (v < bv || (v == bv && id < bc)) { bv = v; bc = id; }
            }
            #pragma unroll
            for (int o = 16; o > 0; o >>= 1) {
                long long ov = __shfl_down_sync(0xffffffffu, bv, o);
                int       oc = __shfl_down_sync(0xffffffffu, bc, o);
                if (ov < bv || (ov == bv && oc < bc)) { bv = ov; bc = oc; }
            }
            if (lane == 0) { g_nn[a] = bc; g_nnd[a] = __longlong_as_double(bv); }
        }
    };

    // ---- deterministic pair detection into s_pia/s_pja (per block) ----
    auto pairs_phase = [&](int na) {
        bool p0 = false, p1 = false;
        int a0 = 0, b0 = 0, a1 = 0, b1 = 0;
        if (t < na) {
            a0 = (int)s_alist[t]; b0 = g_nn[a0];
            const bool mut = (g_nn[b0] == a0);
            p0 = mut && (a0 < b0);
            s_mg[t] = (unsigned char)mut;
        }
        const int t2 = t + NTH;
        if (t2 < na) {
            a1 = (int)s_alist[t2]; b1 = g_nn[a1];
            const bool mut = (g_nn[b1] == a1);
            p1 = mut && (a1 < b1);
            s_mg[t2] = (unsigned char)mut;
        }
        const unsigned m0 = __ballot_sync(0xffffffffu, p0);
        const unsigned m1 = __ballot_sync(0xffffffffu, p1);
        if (lane == 0) { s_wcnt[w] = __popc(m0); s_wcnt[32 + w] = __popc(m1); }
        __syncthreads();
        if (t == 0) {
            int acc = 0;
            #pragma unroll
            for (int q = 0; q < 64; q++) { s_woff[q] = acc; acc += s_wcnt[q]; }
            s_np = acc;
        }
        __syncthreads();
        if (p0) {
            const int pos = s_woff[w] + __popc(m0 & ((1u << lane) - 1u));
            s_pia[pos] = (short)a0; s_pja[pos] = (short)b0;
        }
        if (p1) {
            const int pos = s_woff[32 + w] + __popc(m1 & ((1u << lane) - 1u));
            s_pia[pos] = (short)a1; s_pja[pos] = (short)b1;
        }
        __syncthreads();
    };

    // ---- merge log + parent (only meaningful on block 0) ----
    auto log_phase = [&](int np) {
        const int mbase = g_mcnt;
        for (int p = t; p < np; p += NTH) {
            const int ia = (int)s_pia[p], ja = (int)s_pja[p];
            g_parent[ja] = ia;
            g_md[mbase + p] = g_nnd[ia];
            g_mj[mbase + p] = ja;
        }
        __syncthreads();
        if (t == 0) g_mcnt = mbase + np;
    };

    // ---- Lance-Williams updates: (pair x unmerged) + same-round cross ----
    auto lw_phase = [&](int na, int np, long long start, long long stride) {
        const long long tot1 = (long long)np * na;
        for (long long xw = start; xw < tot1; xw += stride) {
            const int p = (int)(xw / na);
            const int idx = (int)(xw - (long long)p * na);
            if (s_mg[idx]) continue;
            const int m = (int)s_alist[idx];
            const int iA = (int)s_pia[p], jA = (int)s_pja[p];
            const int szi = (int)s_sizes[iA], szj = (int)s_sizes[jA], szm = (int)s_sizes[m];
            const double si = (double)szi, sj = (double)szj;
            const double dij = g_nnd[iA];
            const double sm = (double)szm;
            const double a = g_d2[(size_t)iA * NPTS + m];
            const double b = g_d2[(size_t)jA * NPTS + m];
            const int Ti = szi + szj + szm;
            const double num = ((si + sm) * a + (sj + sm) * b - sm * dij);
            const double nd = div_exact(num, (double)Ti, __ldg(&g_recip[Ti]));
            g_d2[(size_t)iA * NPTS + m] = nd;
            g_d2[(size_t)m * NPTS + iA] = nd;
        }
        const long long tot2 = (long long)np * np;
        for (long long xw = start; xw < tot2; xw += stride) {
            const int p = (int)(xw / np);
            const int q = (int)(xw - (long long)p * np);
            if (p >= q) continue;
            const double dp = g_nnd[(int)s_pia[p]], dq = g_nnd[(int)s_pia[q]];
            int e, l;
            if (dp < dq || (dp == dq && s_pia[p] < s_pia[q])) { e = p; l = q; }
            else                                              { e = q; l = p; }
            const int iE = (int)s_pia[e], jE = (int)s_pja[e];
            const int iL = (int)s_pia[l], jL = (int)s_pja[l];
            const int szE1 = (int)s_sizes[iE], szE2 = (int)s_sizes[jE];
            const int szL1 = (int)s_sizes[iL], szL2 = (int)s_sizes[jL];
            const double siE = (double)szE1, sjE = (double)szE2;
            const double dE = g_nnd[iE];
            const double siL = (double)szL1, sjL = (double)szL2;
            const double dL = g_nnd[iL];
            const double a1c = g_d2[(size_t)iE * NPTS + iL];
            const double b1c = g_d2[(size_t)jE * NPTS + iL];
            const int T1 = szE1 + szE2 + szL1;
            const double u = div_exact((siE + siL) * a1c + (sjE + siL) * b1c - siL * dE,
                                       (double)T1, __ldg(&g_recip[T1]));
            const double a2c = g_d2[(size_t)iE * NPTS + jL];
            const double b2c = g_d2[(size_t)jE * NPTS + jL];
            const int T2 = szE1 + szE2 + szL2;
            const double v = div_exact((siE + sjL) * a2c + (sjE + sjL) * b2c - sjL * dE,
                                       (double)T2, __ldg(&g_recip[T2]));
            const double smE = siE + sjE;
            const int T3 = szL1 + szL2 + szE1 + szE2;
            const double nd = div_exact((siL + smE) * u + (sjL + smE) * v - smE * dL,
                                        (double)T3, __ldg(&g_recip[T3]));
            g_d2[(size_t)iE * NPTS + iL] = nd;
            g_d2[(size_t)iL * NPTS + iE] = nd;
        }
    };

    // ---- block-local sizes update + stable alist compaction ----
    auto post_phase = [&](int na, int np) {
        for (int p = t; p < np; p += NTH)
            s_sizes[(int)s_pia[p]] = (unsigned short)(s_sizes[(int)s_pia[p]] + s_sizes[(int)s_pja[p]]);
        const int i0 = 2 * t, i1 = 2 * t + 1;
        int c = 0;
        unsigned char k0 = 0, k1 = 0;
        if (i0 < na) {
            const int a = (int)s_alist[i0]; s_id[i0] = (short)a;
            const int b = g_nn[a];
            k0 = !((g_nn[b] == a) && (b < a));   // dead iff merged as j
            c += k0;
        }
        if (i1 < na) {
            const int a = (int)s_alist[i1]; s_id[i1] = (short)a;
            const int b = g_nn[a];
            k1 = !((g_nn[b] == a) && (b < a));
            c += k1;
        }
        s_a[t] = c;
        __syncthreads();
        int* src = s_a; int* dst = s_b;
        for (int off = 1; off < NTH; off <<= 1) {
            int v = src[t];
            if (t >= off) v += src[t - off];
            dst[t] = v;
            __syncthreads();
            int* tmp = src; src = dst; dst = tmp;
        }
        int pos = (t > 0) ? src[t - 1] : 0;
        if (i0 < na && k0) s_alist[pos++] = s_id[i0];
        if (i1 < na && k1) s_alist[pos] = s_id[i1];
        if (t == 0) s_na = src[NTH - 1];
        __syncthreads();
    };

    // ================= grid-wide rounds =================
    while (true) {
        const int na = s_na;
        if (na <= THRESH) break;
        nn_phase(gwarp, nwarps, na);
        grid_bar();
        pairs_phase(na);
        const int np = s_np;
        if (blockIdx.x == 0) log_phase(np);
        lw_phase(na, np, gtid, gstride);
        __syncthreads();
        post_phase(na, np);
        grid_bar();
    }

    // ================= single-block endgame (block 0) =================
    if (blockIdx.x == 0) {
        while (true) {
            const int na = s_na;
            if (na <= 1) break;
            nn_phase(w, 32, na);
            __syncthreads();
            pairs_phase(na);
            const int np = s_np;
            log_phase(np);
            lw_phase(na, np, t, NTH);
            __syncthreads();
            post_phase(na, np);
        }

        // ---- tail: sort merge heights, cut, mark, ranks ----
        const int mc = g_mcnt;
        for (int i = t; i < NPTS; i += NTH) s_d[i] = (i < mc) ? g_md[i] : dinf();
        __syncthreads();
        for (int k2 = 2; k2 <= NPTS; k2 <<= 1) {
            for (int jj = k2 >> 1; jj > 0; jj >>= 1) {
                for (int i = t; i < NPTS; i += NTH) {
                    const int ixj = i ^ jj;
                    if (ixj > i) {
                        const bool up = ((i & k2) == 0);
                        const double aa = s_d[i], bb = s_d[ixj];
                        if (up ? (aa > bb) : (aa < bb)) { s_d[i] = bb; s_d[ixj] = aa; }
                    }
                }
                __syncthreads();
            }
        }
        const double theta = s_d[NPTS - K - 1];
        for (int i = t; i < mc; i += NTH)
            if (g_md[i] <= theta) g_active[g_mj[i]] = 0;
        __syncthreads();
        const int e0 = g_active[2 * t], e1 = g_active[2 * t + 1];
        s_a[t] = e0 + e1;
        __syncthreads();
        int* src = s_a; int* dst = s_b;
        for (int off = 1; off < NTH; off <<= 1) {
            int v = src[t];
            if (t >= off) v += src[t - off];
            dst[t] = v;
            __syncthreads();
            int* tmp = src; src = dst; dst = tmp;
        }
        const int base = (t > 0) ? src[t - 1] : 0;
        g_rank[2 * t] = base;
        g_rank[2 * t + 1] = base + e0;
    }
    grid_bar();

    // ---- labels + one-hot writeout (all blocks) ----
    for (int p = gtid; p < NPTS; p += gstride) {
        int c = p;
        while (!g_active[c]) c = g_parent[c];
        const int lab = g_rank[c];
        float* o = out + (size_t)p * K;
        for (int q = 0; q < K; q++) o[q] = (q == lab) ? 1.0f : 0.0f;
    }
}

// ---------------------------------------------------------------------------
extern "C" void kernel_launch(void* const* d_in, const int* in_sizes, int n_in,
                              void* d_out, int out_size) {
    const float* x = (const float*)d_in[0];
    int K = out_size / NPTS;   // out = [B*N, K] one-hot => K from out_size

    static int nsm = 0;
    if (nsm == 0) {
        int v = 0;
        if (cudaDeviceGetAttribute(&v, cudaDevAttrMultiProcessorCount, 0) == cudaSuccess && v > 0)
            nsm = v;
        else
            nsm = 64;
    }

    k_init_sq<<<(NPTS + 255) / 256, 256>>>(x);
    k_init_d2<<<dim3(NPTS / TILE, NPTS / TILE), 256>>>(x);
    k_rnn<<<nsm, NTH>>>((float*)d_out, K);
}

// round 11
// speedup vs baseline: 24.1876x; 1.0469x over previous
#include <cuda_runtime.h>
#include <cuda_bf16.h>
#include <cstdint>

#define NPTS 2048
#define DIMS 96
#define NTH 1024
#define THRESH 64
#define MAXP 1024
#define TILE 32
#define RECIPN (NPTS + 1)

// Device scratch (no runtime allocation allowed)
__device__ double g_d2[(size_t)NPTS * NPTS];      // 32 MB
__device__ double g_sq[NPTS];
__device__ long long g_sqi[NPTS];
__device__ unsigned g_k[NPTS * DIMS];             // x * 2^23 (exact integers)
__device__ int    g_exact;
__device__ double g_recip[RECIPN];
__device__ int    g_nn[NPTS];
__device__ double g_nnd[NPTS];
__device__ int    g_parent[NPTS];
__device__ int    g_active[NPTS];
__device__ int    g_rank[NPTS];
__device__ double g_md[NPTS];
__device__ int    g_mj[NPTS];
__device__ int    g_mcnt;
__device__ unsigned g_arrive;
__device__ volatile unsigned g_release;

__device__ __forceinline__ double dinf() {
    return __longlong_as_double(0x7ff0000000000000LL);
}

// Markstein correctly-rounded division num/T given r = RN(1/T): returns RN(num/T).
__device__ __forceinline__ double div_exact(double num, double T, double r) {
    double q0 = __dmul_rn(num, r);
    double e  = __fma_rn(-T, q0, num);
    return __fma_rn(e, r, q0);
}

// sense-reversal software grid barrier (all blocks co-resident by construction)
__device__ __forceinline__ void grid_bar() {
    __syncthreads();
    if (threadIdx.x == 0) {
        __threadfence();
        unsigned gen = g_release;
        if (atomicAdd(&g_arrive, 1) == gridDim.x - 1) {
            atomicExch(&g_arrive, 0);
            __threadfence();
            g_release = gen + 1;
        } else {
            while (g_release == gen) { __nanosleep(32); }
        }
        __threadfence();
    }
    __syncthreads();
}

// ---------------------------------------------------------------------------
// Init: integer lift of x (k = x * 2^23, exactness-verified), integer and
// fp64 squared norms, bookkeeping.
// ---------------------------------------------------------------------------
__global__ void k_init_sq(const float* __restrict__ x) {
    int i = blockIdx.x * blockDim.x + threadIdx.x;
    if (i >= NPTS) return;
    g_recip[i + 1] = 1.0 / (double)(i + 1);
    if (i == 0) { g_recip[0] = 1.0; g_mcnt = 0; g_arrive = 0; g_release = 0; g_exact = 1; }
    const float* xr = x + (size_t)i * DIMS;
    double acc = 0.0;
    long long acci = 0;
    bool ok = true;
    #pragma unroll 8
    for (int d = 0; d < DIMS; d++) {
        const float xv = xr[d];
        double v = (double)xv;
        acc = fma(v, v, acc);
        unsigned k = (unsigned)(xv * 8388608.0f);
        if (k >= (1u << 23) || (float)k * (1.0f / 8388608.0f) != xv) ok = false;
        g_k[i * DIMS + d] = k;
        acci += (long long)k * (long long)k;
    }
    g_sq[i] = acc;
    g_sqi[i] = acci;
    if (!ok) atomicExch(&g_exact, 0);
    g_parent[i] = i;
    g_active[i] = 1;
}

// ---------------------------------------------------------------------------
// Distance matrix. Fast path: exact int64 Gram via IMAD.WIDE (bit-identical
// to fp64 since all values are integers*2^-46 < 2^53). Fallback: proven
// fp64 serial-fma path if the integer lift was inexact.
// Shared buffer is REUSED by both paths (union via cast) to fit 48KB.
// ---------------------------------------------------------------------------
__global__ void k_init_d2(const float* __restrict__ x) {
    __shared__ unsigned SBUF[2][TILE][DIMS + 1];   // 24.8 KB, shared by both paths
    const int ti = blockIdx.y, tj = blockIdx.x;
    if (tj < ti) return;

    if (g_exact) {
        unsigned (*A)[DIMS + 1] = SBUF[0];
        unsigned (*B)[DIMS + 1] = SBUF[1];
        for (int idx = threadIdx.x; idx < TILE * DIMS; idx += blockDim.x) {
            const int r = idx / DIMS, d = idx - r * DIMS;
            A[r][d] = g_k[(size_t)(ti * TILE + r) * DIMS + d];
            B[r][d] = g_k[(size_t)(tj * TILE + r) * DIMS + d];
        }
        __syncthreads();
        // 2x2 register micro-tile: thread covers rows {r0,r0+1} x cols {c0,c0+1}
        const int r0 = (threadIdx.x >> 4) << 1;          // 0,2,..,30
        const int c0 = (threadIdx.x & 15) << 1;          // 0,2,..,30
        unsigned long long d00 = 0, d01 = 0, d10 = 0, d11 = 0;
        #pragma unroll 8
        for (int d = 0; d < DIMS; d++) {
            const unsigned a0 = A[r0][d], a1 = A[r0 + 1][d];
            const unsigned b0 = B[c0][d], b1 = B[c0 + 1][d];
            d00 += (unsigned long long)a0 * b0;
            d01 += (unsigned long long)a0 * b1;
            d10 += (unsigned long long)a1 * b0;
            d11 += (unsigned long long)a1 * b1;
        }
        #pragma unroll
        for (int rr = 0; rr < 2; rr++) {
            #pragma unroll
            for (int cc = 0; cc < 2; cc++) {
                const int gi = ti * TILE + r0 + rr;
                const int gj = tj * TILE + c0 + cc;
                if (gj < gi) continue;
                double v;
                if (gi == gj) v = dinf();
                else {
                    const unsigned long long dot =
                        (rr == 0) ? (cc == 0 ? d00 : d01) : (cc == 0 ? d10 : d11);
                    const long long num = g_sqi[gi] + g_sqi[gj] - 2ll * (long long)dot;
                    v = (double)num * 0x1p-46;   // exact: num = sum((ki-kj)^2) < 2^53
                }
                g_d2[(size_t)gi * NPTS + gj] = v;
                g_d2[(size_t)gj * NPTS + gi] = v;
            }
        }
    } else {
        // fp64 fallback (identical arithmetic to prior passing kernel)
        float (*A)[DIMS + 1] = reinterpret_cast<float (*)[DIMS + 1]>(SBUF[0]);
        float (*B)[DIMS + 1] = reinterpret_cast<float (*)[DIMS + 1]>(SBUF[1]);
        for (int idx = threadIdx.x; idx < TILE * DIMS; idx += blockDim.x) {
            const int r = idx / DIMS, d = idx - r * DIMS;
            A[r][d] = x[(size_t)(ti * TILE + r) * DIMS + d];
            B[r][d] = x[(size_t)(tj * TILE + r) * DIMS + d];
        }
        __syncthreads();
        #pragma unroll
        for (int e = 0; e < (TILE * TILE) / 256; e++) {
            const int idx = threadIdx.x + e * 256;
            const int r = idx >> 5, c = idx & 31;
            const int gi = ti * TILE + r, gj = tj * TILE + c;
            if (gj < gi) continue;
            if (gi == gj) { g_d2[(size_t)gi * NPTS + gj] = dinf(); continue; }
            double dot = 0.0;
            #pragma unroll 8
            for (int d = 0; d < DIMS; d++) {
                dot = fma((double)A[r][d], (double)B[c][d], dot);
            }
            double v = g_sq[gi] + g_sq[gj] - 2.0 * dot;
            if (v < 0.0) v = 0.0;
            g_d2[(size_t)gi * NPTS + gj] = v;
            g_d2[(size_t)gj * NPTS + gi] = v;
        }
    }
}

// ---------------------------------------------------------------------------
// Persistent RNN-rounds kernel with block-local replicated cluster state.
// ---------------------------------------------------------------------------
__global__ void __launch_bounds__(NTH, 1) k_rnn(float* __restrict__ out, int K) {
    __shared__ short s_alist[NPTS];                  // 4 KB (block-local, replicated)
    __shared__ unsigned short s_sizes[NPTS];         // 4 KB (block-local, replicated)
    __shared__ short s_pia[MAXP], s_pja[MAXP];       // 4 KB
    __shared__ unsigned char s_mg[NPTS];             // 2 KB
    __shared__ short s_id[NPTS];                     // 4 KB
    __shared__ int   s_a[NTH], s_b[NTH];             // 8 KB
    __shared__ double s_d[NPTS];                     // 16 KB (tail sort only)
    __shared__ int   s_wcnt[64], s_woff[64];
    __shared__ int   s_np, s_na;

    const int t = threadIdx.x;
    const int w = t >> 5, lane = t & 31;
    const int gtid = blockIdx.x * NTH + t;
    const int gstride = gridDim.x * NTH;
    const int gwarp = blockIdx.x * 32 + w;
    const int nwarps = gridDim.x * 32;

    for (int r = t; r < NPTS; r += NTH) { s_alist[r] = (short)r; s_sizes[r] = 1; }
    if (t == 0) s_na = NPTS;
    __syncthreads();

    auto nn_phase = [&](int firstRow, int rowStride, int na) {
        for (int r = firstRow; r < na; r += rowStride) {
            const int a = (int)s_alist[r];
            const double* row = g_d2 + (size_t)a * NPTS;
            long long bv = 0x7ff0000000000000LL; int bc = NPTS;
            for (int c = lane; c < na; c += 32) {
                const int id = (int)s_alist[c];
                const long long v = __double_as_longlong(row[id]);
                if (v < bv || (v == bv && id < bc)) { bv = v; bc = id; }
            }
            #pragma unroll
            for (int o = 16; o > 0; o >>= 1) {
                long long ov = __shfl_down_sync(0xffffffffu, bv, o);
                int       oc = __shfl_down_sync(0xffffffffu, bc, o);
                if (ov < bv || (ov == bv && oc < bc)) { bv = ov; bc = oc; }
            }
            if (lane == 0) { g_nn[a] = bc; g_nnd[a] = __longlong_as_double(bv); }
        }
    };

    auto pairs_phase = [&](int na) {
        bool p0 = false, p1 = false;
        int a0 = 0, b0 = 0, a1 = 0, b1 = 0;
        if (t < na) {
            a0 = (int)s_alist[t]; b0 = g_nn[a0];
            const bool mut = (g_nn[b0] == a0);
            p0 = mut && (a0 < b0);
            s_mg[t] = (unsigned char)mut;
        }
        const int t2 = t + NTH;
        if (t2 < na) {
            a1 = (int)s_alist[t2]; b1 = g_nn[a1];
            const bool mut = (g_nn[b1] == a1);
            p1 = mut && (a1 < b1);
            s_mg[t2] = (unsigned char)mut;
        }
        const unsigned m0 = __ballot_sync(0xffffffffu, p0);
        const unsigned m1 = __ballot_sync(0xffffffffu, p1);
        if (lane == 0) { s_wcnt[w] = __popc(m0); s_wcnt[32 + w] = __popc(m1); }
        __syncthreads();
        if (t == 0) {
            int acc = 0;
            #pragma unroll
            for (int q = 0; q < 64; q++) { s_woff[q] = acc; acc += s_wcnt[q]; }
            s_np = acc;
        }
        __syncthreads();
        if (p0) {
            const int pos = s_woff[w] + __popc(m0 & ((1u << lane) - 1u));
            s_pia[pos] = (short)a0; s_pja[pos] = (short)b0;
        }
        if (p1) {
            const int pos = s_woff[32 + w] + __popc(m1 & ((1u << lane) - 1u));
            s_pia[pos] = (short)a1; s_pja[pos] = (short)b1;
        }
        __syncthreads();
    };

    auto log_phase = [&](int np) {
        const int mbase = g_mcnt;
        for (int p = t; p < np; p += NTH) {
            const int ia = (int)s_pia[p], ja = (int)s_pja[p];
            g_parent[ja] = ia;
            g_md[mbase + p] = g_nnd[ia];
            g_mj[mbase + p] = ja;
        }
        __syncthreads();
        if (t == 0) g_mcnt = mbase + np;
    };

    auto lw_phase = [&](int na, int np, long long start, long long stride) {
        const long long tot1 = (long long)np * na;
        for (long long xw = start; xw < tot1; xw += stride) {
            const int p = (int)(xw / na);
            const int idx = (int)(xw - (long long)p * na);
            if (s_mg[idx]) continue;
            const int m = (int)s_alist[idx];
            const int iA = (int)s_pia[p], jA = (int)s_pja[p];
            const int szi = (int)s_sizes[iA], szj = (int)s_sizes[jA], szm = (int)s_sizes[m];
            const double si = (double)szi, sj = (double)szj;
            const double dij = g_nnd[iA];
            const double sm = (double)szm;
            const double a = g_d2[(size_t)iA * NPTS + m];
            const double b = g_d2[(size_t)jA * NPTS + m];
            const int Ti = szi + szj + szm;
            const double num = ((si + sm) * a + (sj + sm) * b - sm * dij);
            const double nd = div_exact(num, (double)Ti, __ldg(&g_recip[Ti]));
            g_d2[(size_t)iA * NPTS + m] = nd;
            g_d2[(size_t)m * NPTS + iA] = nd;
        }
        const long long tot2 = (long long)np * np;
        for (long long xw = start; xw < tot2; xw += stride) {
            const int p = (int)(xw / np);
            const int q = (int)(xw - (long long)p * np);
            if (p >= q) continue;
            const double dp = g_nnd[(int)s_pia[p]], dq = g_nnd[(int)s_pia[q]];
            int e, l;
            if (dp < dq || (dp == dq && s_pia[p] < s_pia[q])) { e = p; l = q; }
            else                                              { e = q; l = p; }
            const int iE = (int)s_pia[e], jE = (int)s_pja[e];
            const int iL = (int)s_pia[l], jL = (int)s_pja[l];
            const int szE1 = (int)s_sizes[iE], szE2 = (int)s_sizes[jE];
            const int szL1 = (int)s_sizes[iL], szL2 = (int)s_sizes[jL];
            const double siE = (double)szE1, sjE = (double)szE2;
            const double dE = g_nnd[iE];
            const double siL = (double)szL1, sjL = (double)szL2;
            const double dL = g_nnd[iL];
            const double a1c = g_d2[(size_t)iE * NPTS + iL];
            const double b1c = g_d2[(size_t)jE * NPTS + iL];
            const int T1 = szE1 + szE2 + szL1;
            const double u = div_exact((siE + siL) * a1c + (sjE + siL) * b1c - siL * dE,
                                       (double)T1, __ldg(&g_recip[T1]));
            const double a2c = g_d2[(size_t)iE * NPTS + jL];
            const double b2c = g_d2[(size_t)jE * NPTS + jL];
            const int T2 = szE1 + szE2 + szL2;
            const double v = div_exact((siE + sjL) * a2c + (sjE + sjL) * b2c - sjL * dE,
                                       (double)T2, __ldg(&g_recip[T2]));
            const double smE = siE + sjE;
            const int T3 = szL1 + szL2 + szE1 + szE2;
            const double nd = div_exact((siL + smE) * u + (sjL + smE) * v - smE * dL,
                                        (double)T3, __ldg(&g_recip[T3]));
            g_d2[(size_t)iE * NPTS + iL] = nd;
            g_d2[(size_t)iL * NPTS + iE] = nd;
        }
    };

    auto post_phase = [&](int na, int np) {
        for (int p = t; p < np; p += NTH)
            s_sizes[(int)s_pia[p]] = (unsigned short)(s_sizes[(int)s_pia[p]] + s_sizes[(int)s_pja[p]]);
        const int i0 = 2 * t, i1 = 2 * t + 1;
        int c = 0;
        unsigned char k0 = 0, k1 = 0;
        if (i0 < na) {
            const int a = (int)s_alist[i0]; s_id[i0] = (short)a;
            const int b = g_nn[a];
            k0 = !((g_nn[b] == a) && (b < a));
            c += k0;
        }
        if (i1 < na) {
            const int a = (int)s_alist[i1]; s_id[i1] = (short)a;
            const int b = g_nn[a];
            k1 = !((g_nn[b] == a) && (b < a));
            c += k1;
        }
        s_a[t] = c;
        __syncthreads();
        int* src = s_a; int* dst = s_b;
        for (int off = 1; off < NTH; off <<= 1) {
            int v = src[t];
            if (t >= off) v += src[t - off];
            dst[t] = v;
            __syncthreads();
            int* tmp = src; src = dst; dst = tmp;
        }
        int pos = (t > 0) ? src[t - 1] : 0;
        if (i0 < na && k0) s_alist[pos++] = s_id[i0];
        if (i1 < na && k1) s_alist[pos] = s_id[i1];
        if (t == 0) s_na = src[NTH - 1];
        __syncthreads();
    };

    // ================= grid-wide rounds =================
    while (true) {
        const int na = s_na;
        if (na <= THRESH) break;
        nn_phase(gwarp, nwarps, na);
        grid_bar();
        pairs_phase(na);
        const int np = s_np;
        if (blockIdx.x == 0) log_phase(np);
        lw_phase(na, np, gtid, gstride);
        __syncthreads();
        post_phase(na, np);
        grid_bar();
    }

    // ================= single-block endgame (block 0) =================
    if (blockIdx.x == 0) {
        while (true) {
            const int na = s_na;
            if (na <= 1) break;
            nn_phase(w, 32, na);
            __syncthreads();
            pairs_phase(na);
            const int np = s_np;
            log_phase(np);
            lw_phase(na, np, t, NTH);
            __syncthreads();
            post_phase(na, np);
        }

        const int mc = g_mcnt;
        for (int i = t; i < NPTS; i += NTH) s_d[i] = (i < mc) ? g_md[i] : dinf();
        __syncthreads();
        for (int k2 = 2; k2 <= NPTS; k2 <<= 1) {
            for (int jj = k2 >> 1; jj > 0; jj >>= 1) {
                for (int i = t; i < NPTS; i += NTH) {
                    const int ixj = i ^ jj;
                    if (ixj > i) {
                        const bool up = ((i & k2) == 0);
                        const double aa = s_d[i], bb = s_d[ixj];
                        if (up ? (aa > bb) : (aa < bb)) { s_d[i] = bb; s_d[ixj] = aa; }
                    }
                }
                __syncthreads();
            }
        }
        const double theta = s_d[NPTS - K - 1];
        for (int i = t; i < mc; i += NTH)
            if (g_md[i] <= theta) g_active[g_mj[i]] = 0;
        __syncthreads();
        const int e0 = g_active[2 * t], e1 = g_active[2 * t + 1];
        s_a[t] = e0 + e1;
        __syncthreads();
        int* src = s_a; int* dst = s_b;
        for (int off = 1; off < NTH; off <<= 1) {
            int v = src[t];
            if (t >= off) v += src[t - off];
            dst[t] = v;
            __syncthreads();
            int* tmp = src; src = dst; dst = tmp;
        }
        const int base = (t > 0) ? src[t - 1] : 0;
        g_rank[2 * t] = base;
        g_rank[2 * t + 1] = base + e0;
    }
    grid_bar();

    for (int p = gtid; p < NPTS; p += gstride) {
        int c = p;
        while (!g_active[c]) c = g_parent[c];
        const int lab = g_rank[c];
        float* o = out + (size_t)p * K;
        for (int q = 0; q < K; q++) o[q] = (q == lab) ? 1.0f : 0.0f;
    }
}

// ---------------------------------------------------------------------------
extern "C" void kernel_launch(void* const* d_in, const int* in_sizes, int n_in,
                              void* d_out, int out_size) {
    const float* x = (const float*)d_in[0];
    int K = out_size / NPTS;   // out = [B*N, K] one-hot => K from out_size

    static int nsm = 0;
    if (nsm == 0) {
        int v = 0;
        if (cudaDeviceGetAttribute(&v, cudaDevAttrMultiProcessorCount, 0) == cudaSuccess && v > 0)
            nsm = v;
        else
            nsm = 64;
    }

    k_init_sq<<<(NPTS + 255) / 256, 256>>>(x);
    k_init_d2<<<dim3(NPTS / TILE, NPTS / TILE), 256>>>(x);
    k_rnn<<<nsm, NTH>>>((float*)d_out, K);
}